// round 1
// baseline (speedup 1.0000x reference)
#include <cuda_runtime.h>
#include <cuda_bf16.h>

// ---------------------------------------------------------------------------
// LlamaAttention: hidden(2048x4096) -> QKV proj -> RoPE -> causal flash attn
// -> output proj. All fp32 baseline.
// Shapes: S=2048, HID=4096, NH=32, NKV=8, D=128.
// ---------------------------------------------------------------------------

#define S_LEN 2048
#define HID   4096
#define NH    32
#define NKV   8
#define HD    128
#define KVDIM (NKV * HD)   // 1024

// scratch (device globals; no allocation allowed)
__device__ float g_q[S_LEN * HID];
__device__ float g_k[S_LEN * KVDIM];
__device__ float g_v[S_LEN * KVDIM];
__device__ float g_attn[S_LEN * HID];

// ---------------------------------------------------------------------------
// SGEMM: C[M,N] = A[M,K] @ B[N,K]^T   (A,B,C row-major; B is a weight [N,K])
// BM=BN=128, BK=8, 256 threads, 8x8 microtile per thread.
// ---------------------------------------------------------------------------
#define BM 128
#define BN 128
#define BKk 8

__global__ __launch_bounds__(256) void sgemm_nt(const float* __restrict__ A,
                                                const float* __restrict__ B,
                                                float* __restrict__ C,
                                                int M, int N, int K) {
    __shared__ float As[BKk][BM];
    __shared__ float Bs[BKk][BN];

    const int tid = threadIdx.x;
    const int tx = tid & 15;
    const int ty = tid >> 4;
    const int bm = blockIdx.y * BM;
    const int bn = blockIdx.x * BN;

    float acc[8][8];
#pragma unroll
    for (int i = 0; i < 8; i++)
#pragma unroll
        for (int j = 0; j < 8; j++) acc[i][j] = 0.f;

    const int lr = tid >> 1;          // 0..127
    const int lk = (tid & 1) * 4;     // 0 or 4

    for (int k0 = 0; k0 < K; k0 += BKk) {
        float4 a4 = *(const float4*)(A + (size_t)(bm + lr) * K + k0 + lk);
        float4 b4 = *(const float4*)(B + (size_t)(bn + lr) * K + k0 + lk);
        As[lk + 0][lr] = a4.x; As[lk + 1][lr] = a4.y;
        As[lk + 2][lr] = a4.z; As[lk + 3][lr] = a4.w;
        Bs[lk + 0][lr] = b4.x; Bs[lk + 1][lr] = b4.y;
        Bs[lk + 2][lr] = b4.z; Bs[lk + 3][lr] = b4.w;
        __syncthreads();

#pragma unroll
        for (int k = 0; k < BKk; k++) {
            float a[8], b[8];
#pragma unroll
            for (int i = 0; i < 8; i++) a[i] = As[k][ty + i * 16];
#pragma unroll
            for (int j = 0; j < 8; j++) b[j] = Bs[k][tx + j * 16];
#pragma unroll
            for (int i = 0; i < 8; i++)
#pragma unroll
                for (int j = 0; j < 8; j++) acc[i][j] = fmaf(a[i], b[j], acc[i][j]);
        }
        __syncthreads();
    }

#pragma unroll
    for (int i = 0; i < 8; i++) {
        const int r = bm + ty + i * 16;
#pragma unroll
        for (int j = 0; j < 8; j++) {
            C[(size_t)r * N + bn + tx + j * 16] = acc[i][j];
        }
    }
}

// ---------------------------------------------------------------------------
// RoPE (interleaved pairs), applied in-place to q[S,32,128] and k[S,8,128]
// ---------------------------------------------------------------------------
__global__ void rope_kernel(float* __restrict__ q, float* __restrict__ k,
                            const float* __restrict__ cosb,
                            const float* __restrict__ sinb) {
    int idx = blockIdx.x * blockDim.x + threadIdx.x;
    const int total = S_LEN * (NH + NKV) * (HD / 2);
    if (idx >= total) return;
    int i = idx & 63;              // 0..63 rotation index
    int h = (idx >> 6) % (NH + NKV);
    int s = idx / (64 * (NH + NKV));
    float c  = cosb[s * 64 + i];
    float sn = sinb[s * 64 + i];
    float* base;
    if (h < NH) base = q + (size_t)s * HID + h * HD;
    else        base = k + (size_t)s * KVDIM + (h - NH) * HD;
    float a = base[2 * i];
    float b = base[2 * i + 1];
    base[2 * i]     = a * c - b * sn;
    base[2 * i + 1] = a * sn + b * c;
}

// ---------------------------------------------------------------------------
// Causal flash attention (fp32).
// Grid: (qblock=32, head=32). 256 threads.
// BQ=BKV=64, D=128. Thread (ty 0..15, tx 0..15): rows ty*4..+3,
// S cols tx + cj*16, O cols tx + dd*16.
// SMEM: Qs/Ks/Vs with row stride SD=132 (pad), Ps 64x64.
// ---------------------------------------------------------------------------
#define BQ  64
#define BKV 64
#define SD  132
#define FLASH_SMEM ((3 * BQ * SD + BQ * BKV) * 4)

__global__ __launch_bounds__(256) void flash_kernel(const float* __restrict__ q,
                                                    const float* __restrict__ k,
                                                    const float* __restrict__ v,
                                                    float* __restrict__ o) {
    extern __shared__ float sm[];
    float* Qs = sm;                    // BQ * SD
    float* Ks = Qs + BQ * SD;          // BKV * SD
    float* Vs = Ks + BKV * SD;         // BKV * SD
    float* Ps = Vs + BKV * SD;         // BQ * BKV

    const int qb = blockIdx.x;
    const int h  = blockIdx.y;
    const int kvh = h >> 2;
    const int tid = threadIdx.x;
    const int tx = tid & 15;
    const int ty = tid >> 4;
    const int q0 = qb * BQ;
    const float scale = 0.08838834764831845f;  // 1/sqrt(128)

    // load Q tile
    for (int i = tid; i < BQ * HD / 4; i += 256) {
        int r = i >> 5;            // 32 float4 per row
        int c = (i & 31) * 4;
        *(float4*)&Qs[r * SD + c] =
            *(const float4*)&q[(size_t)(q0 + r) * HID + h * HD + c];
    }

    float m[4], l[4], acc[4][8];
#pragma unroll
    for (int i = 0; i < 4; i++) {
        m[i] = -1e30f; l[i] = 0.f;
#pragma unroll
        for (int j = 0; j < 8; j++) acc[i][j] = 0.f;
    }
    __syncthreads();

    for (int kb = 0; kb <= qb; kb++) {
        const int k0 = kb * BKV;
        for (int i = tid; i < BKV * HD / 4; i += 256) {
            int r = i >> 5;
            int c = (i & 31) * 4;
            *(float4*)&Ks[r * SD + c] =
                *(const float4*)&k[(size_t)(k0 + r) * KVDIM + kvh * HD + c];
            *(float4*)&Vs[r * SD + c] =
                *(const float4*)&v[(size_t)(k0 + r) * KVDIM + kvh * HD + c];
        }
        __syncthreads();

        // S = Q K^T for rows ty*4..+3, cols tx+cj*16
        float s[4][4];
#pragma unroll
        for (int ri = 0; ri < 4; ri++)
#pragma unroll
            for (int cj = 0; cj < 4; cj++) s[ri][cj] = 0.f;

        for (int d = 0; d < HD; d += 4) {
            float4 qv[4], kv[4];
#pragma unroll
            for (int ri = 0; ri < 4; ri++)
                qv[ri] = *(const float4*)&Qs[(ty * 4 + ri) * SD + d];
#pragma unroll
            for (int cj = 0; cj < 4; cj++)
                kv[cj] = *(const float4*)&Ks[(tx + cj * 16) * SD + d];
#pragma unroll
            for (int ri = 0; ri < 4; ri++)
#pragma unroll
                for (int cj = 0; cj < 4; cj++) {
                    s[ri][cj] = fmaf(qv[ri].x, kv[cj].x, s[ri][cj]);
                    s[ri][cj] = fmaf(qv[ri].y, kv[cj].y, s[ri][cj]);
                    s[ri][cj] = fmaf(qv[ri].z, kv[cj].z, s[ri][cj]);
                    s[ri][cj] = fmaf(qv[ri].w, kv[cj].w, s[ri][cj]);
                }
        }

        // scale + causal mask
        const bool diag = (kb == qb);
#pragma unroll
        for (int ri = 0; ri < 4; ri++) {
            const int gi = q0 + ty * 4 + ri;
#pragma unroll
            for (int cj = 0; cj < 4; cj++) {
                const int gj = k0 + tx + cj * 16;
                s[ri][cj] *= scale;
                if (diag && gj > gi) s[ri][cj] = -1e30f;
            }
        }

        // online softmax per row (16-lane shuffle reduce)
#pragma unroll
        for (int ri = 0; ri < 4; ri++) {
            float mx = fmaxf(fmaxf(s[ri][0], s[ri][1]), fmaxf(s[ri][2], s[ri][3]));
#pragma unroll
            for (int off = 8; off >= 1; off >>= 1)
                mx = fmaxf(mx, __shfl_xor_sync(0xffffffffu, mx, off));
            const float mnew = fmaxf(m[ri], mx);
            const float corr = __expf(m[ri] - mnew);
            float rs = 0.f;
            const int row = ty * 4 + ri;
#pragma unroll
            for (int cj = 0; cj < 4; cj++) {
                float p = __expf(s[ri][cj] - mnew);
                Ps[row * BKV + tx + cj * 16] = p;
                rs += p;
            }
#pragma unroll
            for (int off = 8; off >= 1; off >>= 1)
                rs += __shfl_xor_sync(0xffffffffu, rs, off);
            l[ri] = l[ri] * corr + rs;
            m[ri] = mnew;
#pragma unroll
            for (int dd = 0; dd < 8; dd++) acc[ri][dd] *= corr;
        }
        __syncwarp();

        // O += P @ V  (thread: rows ty*4..+3, dcols tx+dd*16)
        for (int j = 0; j < BKV; j++) {
            float pv[4];
#pragma unroll
            for (int ri = 0; ri < 4; ri++) pv[ri] = Ps[(ty * 4 + ri) * BKV + j];
            float vv[8];
#pragma unroll
            for (int dd = 0; dd < 8; dd++) vv[dd] = Vs[j * SD + tx + dd * 16];
#pragma unroll
            for (int ri = 0; ri < 4; ri++)
#pragma unroll
                for (int dd = 0; dd < 8; dd++)
                    acc[ri][dd] = fmaf(pv[ri], vv[dd], acc[ri][dd]);
        }
        __syncthreads();
    }

    // epilogue: normalize and store to attn[s, h, d]
#pragma unroll
    for (int ri = 0; ri < 4; ri++) {
        const int gi = q0 + ty * 4 + ri;
        const float inv = 1.0f / l[ri];
#pragma unroll
        for (int dd = 0; dd < 8; dd++) {
            o[(size_t)gi * HID + h * HD + tx + dd * 16] = acc[ri][dd] * inv;
        }
    }
}

// ---------------------------------------------------------------------------
// launcher
// ---------------------------------------------------------------------------
extern "C" void kernel_launch(void* const* d_in, const int* in_sizes, int n_in,
                              void* d_out, int out_size) {
    const float* hidden = (const float*)d_in[0];
    // d_in[1] = attention_mask (causal; computed analytically, unused)
    const float* cosb = (const float*)d_in[2];
    const float* sinb = (const float*)d_in[3];
    const float* wq = (const float*)d_in[4];
    const float* wk = (const float*)d_in[5];
    const float* wv = (const float*)d_in[6];
    const float* wo = (const float*)d_in[7];
    float* out = (float*)d_out;

    float *q, *k, *v, *attn;
    cudaGetSymbolAddress((void**)&q, g_q);
    cudaGetSymbolAddress((void**)&k, g_k);
    cudaGetSymbolAddress((void**)&v, g_v);
    cudaGetSymbolAddress((void**)&attn, g_attn);

    // QKV projections
    sgemm_nt<<<dim3(HID / BN, S_LEN / BM), 256>>>(hidden, wq, q, S_LEN, HID, HID);
    sgemm_nt<<<dim3(KVDIM / BN, S_LEN / BM), 256>>>(hidden, wk, k, S_LEN, KVDIM, HID);
    sgemm_nt<<<dim3(KVDIM / BN, S_LEN / BM), 256>>>(hidden, wv, v, S_LEN, KVDIM, HID);

    // RoPE
    {
        int total = S_LEN * (NH + NKV) * (HD / 2);
        rope_kernel<<<(total + 255) / 256, 256>>>(q, k, cosb, sinb);
    }

    // flash attention
    cudaFuncSetAttribute(flash_kernel, cudaFuncAttributeMaxDynamicSharedMemorySize,
                         FLASH_SMEM);
    flash_kernel<<<dim3(S_LEN / BQ, NH), 256, FLASH_SMEM>>>(q, k, v, attn);

    // output projection
    sgemm_nt<<<dim3(HID / BN, S_LEN / BM), 256>>>(attn, wo, out, S_LEN, HID, HID);
}

// round 2
// speedup vs baseline: 2.2401x; 2.2401x over previous
#include <cuda_runtime.h>
#include <cuda_bf16.h>
#include <stdint.h>

// ---------------------------------------------------------------------------
// LlamaAttention: S=2048, HID=4096, NH=32, NKV=8, D=128
// GEMMs via bf16x3 split + mma.sync tensor cores (fp32-class accuracy).
// Flash attention fp32.
// ---------------------------------------------------------------------------

#define S_LEN 2048
#define HID   4096
#define NH    32
#define NKV   8
#define HD    128
#define KVDIM (NKV * HD)   // 1024

// fp32 scratch
__device__ float g_q[S_LEN * HID];
__device__ float g_k[S_LEN * KVDIM];
__device__ float g_v[S_LEN * KVDIM];
__device__ float g_attn[S_LEN * HID];

// bf16 split scratch (hi + lo)
__device__ __nv_bfloat16 g_hid_hi[S_LEN * HID];
__device__ __nv_bfloat16 g_hid_lo[S_LEN * HID];
__device__ __nv_bfloat16 g_wq_hi[HID * HID];
__device__ __nv_bfloat16 g_wq_lo[HID * HID];
__device__ __nv_bfloat16 g_wk_hi[KVDIM * HID];
__device__ __nv_bfloat16 g_wk_lo[KVDIM * HID];
__device__ __nv_bfloat16 g_wv_hi[KVDIM * HID];
__device__ __nv_bfloat16 g_wv_lo[KVDIM * HID];
__device__ __nv_bfloat16 g_wo_hi[HID * HID];
__device__ __nv_bfloat16 g_wo_lo[HID * HID];
__device__ __nv_bfloat16 g_attn_hi[S_LEN * HID];
__device__ __nv_bfloat16 g_attn_lo[S_LEN * HID];

// ---------------------------------------------------------------------------
// split fp32 -> bf16 hi + lo residual
// ---------------------------------------------------------------------------
__global__ void split_bf16(const float* __restrict__ x,
                           __nv_bfloat16* __restrict__ hi,
                           __nv_bfloat16* __restrict__ lo, int n) {
    int i = (blockIdx.x * blockDim.x + threadIdx.x) * 4;
    if (i >= n) return;
    float4 f = *(const float4*)(x + i);
    __nv_bfloat16 h0 = __float2bfloat16(f.x);
    __nv_bfloat16 h1 = __float2bfloat16(f.y);
    __nv_bfloat16 h2 = __float2bfloat16(f.z);
    __nv_bfloat16 h3 = __float2bfloat16(f.w);
    __nv_bfloat16 l0 = __float2bfloat16(f.x - __bfloat162float(h0));
    __nv_bfloat16 l1 = __float2bfloat16(f.y - __bfloat162float(h1));
    __nv_bfloat16 l2 = __float2bfloat16(f.z - __bfloat162float(h2));
    __nv_bfloat16 l3 = __float2bfloat16(f.w - __bfloat162float(h3));
    ushort4 hv, lv;
    hv.x = *(unsigned short*)&h0; hv.y = *(unsigned short*)&h1;
    hv.z = *(unsigned short*)&h2; hv.w = *(unsigned short*)&h3;
    lv.x = *(unsigned short*)&l0; lv.y = *(unsigned short*)&l1;
    lv.z = *(unsigned short*)&l2; lv.w = *(unsigned short*)&l3;
    *(ushort4*)(hi + i) = hv;
    *(ushort4*)(lo + i) = lv;
}

// ---------------------------------------------------------------------------
// bf16x3 GEMM: C[M,N] = Ah·Bh^T + Ah·Bl^T + Al·Bh^T (fp32 accum/out)
// A[M,K], B[N,K] row-major bf16. BM=BN=128, BK=32, 256 thr, 2-stage cp.async.
// ---------------------------------------------------------------------------
#define GBM 128
#define GBN 128
#define GBK 32
#define LDT_B 80                      // padded row: 40 bf16 = 80 bytes
#define TILE_B (128 * LDT_B)          // 10240 bytes per matrix tile
#define STAGE_B (4 * TILE_B)          // Ah, Al, Bh, Bl
#define GEMM_SMEM (2 * STAGE_B)       // 81920

__device__ __forceinline__ void ldsm_x4(uint32_t addr, uint32_t& r0, uint32_t& r1,
                                        uint32_t& r2, uint32_t& r3) {
    asm volatile("ldmatrix.sync.aligned.m8n8.x4.shared.b16 {%0,%1,%2,%3}, [%4];"
                 : "=r"(r0), "=r"(r1), "=r"(r2), "=r"(r3) : "r"(addr));
}

__device__ __forceinline__ void mma_bf16(float* c, const uint32_t* a, const uint32_t* b) {
    asm volatile(
        "mma.sync.aligned.m16n8k16.row.col.f32.bf16.bf16.f32 "
        "{%0,%1,%2,%3},{%4,%5,%6,%7},{%8,%9},{%0,%1,%2,%3};"
        : "+f"(c[0]), "+f"(c[1]), "+f"(c[2]), "+f"(c[3])
        : "r"(a[0]), "r"(a[1]), "r"(a[2]), "r"(a[3]), "r"(b[0]), "r"(b[1]));
}

__global__ __launch_bounds__(256, 1) void gemm_bf16x3(
    const __nv_bfloat16* __restrict__ Ah, const __nv_bfloat16* __restrict__ Al,
    const __nv_bfloat16* __restrict__ Bh, const __nv_bfloat16* __restrict__ Bl,
    float* __restrict__ C, int M, int N, int K) {
    extern __shared__ char smem[];
    const int tid = threadIdx.x;
    const int lane = tid & 31;
    const int warp = tid >> 5;
    const int wr = warp >> 2;       // 0..1
    const int wc = warp & 3;        // 0..3
    const int bm = blockIdx.y * GBM;
    const int bn = blockIdx.x * GBN;
    uint32_t sbase = (uint32_t)__cvta_generic_to_shared(smem);

    float acc[4][4][4];
#pragma unroll
    for (int mi = 0; mi < 4; mi++)
#pragma unroll
        for (int ni = 0; ni < 4; ni++)
#pragma unroll
            for (int t = 0; t < 4; t++) acc[mi][ni][t] = 0.f;

    const __nv_bfloat16* mats[4] = {Ah, Al, Bh, Bl};

    auto load_stage = [&](int s, int k0) {
#pragma unroll
        for (int i = 0; i < 8; i++) {
            int c = tid + i * 256;
            int mat = c >> 9;
            int row = (c >> 2) & 127;
            int ch = c & 3;
            int grow = (mat < 2 ? bm : bn) + row;
            const void* gptr = mats[mat] + (size_t)grow * K + k0 + ch * 8;
            uint32_t daddr = sbase + s * STAGE_B + mat * TILE_B + row * LDT_B + ch * 16;
            asm volatile("cp.async.cg.shared.global [%0], [%1], 16;"
                         :: "r"(daddr), "l"(gptr));
        }
        asm volatile("cp.async.commit_group;");
    };

    const int NIT = K / GBK;
    load_stage(0, 0);

    for (int it = 0; it < NIT; it++) {
        if (it + 1 < NIT) {
            load_stage((it + 1) & 1, (it + 1) * GBK);
            asm volatile("cp.async.wait_group 1;");
        } else {
            asm volatile("cp.async.wait_group 0;");
        }
        __syncthreads();

        uint32_t sa = sbase + (it & 1) * STAGE_B;
#pragma unroll
        for (int ks = 0; ks < 2; ks++) {
            uint32_t ah[4][4], al[4][4];
#pragma unroll
            for (int mi = 0; mi < 4; mi++) {
                uint32_t off = (uint32_t)((wr * 64 + mi * 16 + (lane & 15)) * LDT_B +
                                          ks * 32 + ((lane >> 4) & 1) * 16);
                ldsm_x4(sa + off, ah[mi][0], ah[mi][1], ah[mi][2], ah[mi][3]);
                ldsm_x4(sa + TILE_B + off, al[mi][0], al[mi][1], al[mi][2], al[mi][3]);
            }
            uint32_t bh[4][2], bl[4][2];
#pragma unroll
            for (int np = 0; np < 2; np++) {
                int brow = (lane & 7) + ((lane >> 4) << 3);
                int bch = (lane >> 3) & 1;
                uint32_t off = (uint32_t)((wc * 32 + np * 16 + brow) * LDT_B +
                                          ks * 32 + bch * 16);
                uint32_t r0, r1, r2, r3;
                ldsm_x4(sa + 2 * TILE_B + off, r0, r1, r2, r3);
                bh[np * 2][0] = r0; bh[np * 2][1] = r1;
                bh[np * 2 + 1][0] = r2; bh[np * 2 + 1][1] = r3;
                ldsm_x4(sa + 3 * TILE_B + off, r0, r1, r2, r3);
                bl[np * 2][0] = r0; bl[np * 2][1] = r1;
                bl[np * 2 + 1][0] = r2; bl[np * 2 + 1][1] = r3;
            }
#pragma unroll
            for (int mi = 0; mi < 4; mi++)
#pragma unroll
                for (int ni = 0; ni < 4; ni++) {
                    mma_bf16(acc[mi][ni], ah[mi], bh[ni]);
                    mma_bf16(acc[mi][ni], ah[mi], bl[ni]);
                    mma_bf16(acc[mi][ni], al[mi], bh[ni]);
                }
        }
        __syncthreads();
    }

    // epilogue
#pragma unroll
    for (int mi = 0; mi < 4; mi++) {
        const int r0 = bm + wr * 64 + mi * 16 + (lane >> 2);
#pragma unroll
        for (int ni = 0; ni < 4; ni++) {
            const int col = bn + wc * 32 + ni * 8 + (lane & 3) * 2;
            float2 v01 = make_float2(acc[mi][ni][0], acc[mi][ni][1]);
            float2 v23 = make_float2(acc[mi][ni][2], acc[mi][ni][3]);
            *(float2*)&C[(size_t)r0 * N + col] = v01;
            *(float2*)&C[(size_t)(r0 + 8) * N + col] = v23;
        }
    }
}

// ---------------------------------------------------------------------------
// RoPE (interleaved pairs), in-place on q[S,32,128], k[S,8,128]
// ---------------------------------------------------------------------------
__global__ void rope_kernel(float* __restrict__ q, float* __restrict__ k,
                            const float* __restrict__ cosb,
                            const float* __restrict__ sinb) {
    int idx = blockIdx.x * blockDim.x + threadIdx.x;
    const int total = S_LEN * (NH + NKV) * (HD / 2);
    if (idx >= total) return;
    int i = idx & 63;
    int h = (idx >> 6) % (NH + NKV);
    int s = idx / (64 * (NH + NKV));
    float c  = cosb[s * 64 + i];
    float sn = sinb[s * 64 + i];
    float* base;
    if (h < NH) base = q + (size_t)s * HID + h * HD;
    else        base = k + (size_t)s * KVDIM + (h - NH) * HD;
    float a = base[2 * i];
    float b = base[2 * i + 1];
    base[2 * i]     = a * c - b * sn;
    base[2 * i + 1] = a * sn + b * c;
}

// ---------------------------------------------------------------------------
// Causal flash attention (fp32). Grid (32, 32), 256 threads, BQ=BKV=64.
// ---------------------------------------------------------------------------
#define BQ  64
#define BKV 64
#define SD  132
#define FLASH_SMEM ((3 * BQ * SD + BQ * BKV) * 4)

__global__ __launch_bounds__(256) void flash_kernel(const float* __restrict__ q,
                                                    const float* __restrict__ k,
                                                    const float* __restrict__ v,
                                                    float* __restrict__ o) {
    extern __shared__ float sm[];
    float* Qs = sm;
    float* Ks = Qs + BQ * SD;
    float* Vs = Ks + BKV * SD;
    float* Ps = Vs + BKV * SD;

    const int qb = blockIdx.x;
    const int h  = blockIdx.y;
    const int kvh = h >> 2;
    const int tid = threadIdx.x;
    const int tx = tid & 15;
    const int ty = tid >> 4;
    const int q0 = qb * BQ;
    const float scale = 0.08838834764831845f;

    for (int i = tid; i < BQ * HD / 4; i += 256) {
        int r = i >> 5;
        int c = (i & 31) * 4;
        *(float4*)&Qs[r * SD + c] =
            *(const float4*)&q[(size_t)(q0 + r) * HID + h * HD + c];
    }

    float m[4], l[4], acc[4][8];
#pragma unroll
    for (int i = 0; i < 4; i++) {
        m[i] = -1e30f; l[i] = 0.f;
#pragma unroll
        for (int j = 0; j < 8; j++) acc[i][j] = 0.f;
    }
    __syncthreads();

    for (int kb = 0; kb <= qb; kb++) {
        const int k0 = kb * BKV;
        for (int i = tid; i < BKV * HD / 4; i += 256) {
            int r = i >> 5;
            int c = (i & 31) * 4;
            *(float4*)&Ks[r * SD + c] =
                *(const float4*)&k[(size_t)(k0 + r) * KVDIM + kvh * HD + c];
            *(float4*)&Vs[r * SD + c] =
                *(const float4*)&v[(size_t)(k0 + r) * KVDIM + kvh * HD + c];
        }
        __syncthreads();

        float s[4][4];
#pragma unroll
        for (int ri = 0; ri < 4; ri++)
#pragma unroll
            for (int cj = 0; cj < 4; cj++) s[ri][cj] = 0.f;

        for (int d = 0; d < HD; d += 4) {
            float4 qv[4], kv[4];
#pragma unroll
            for (int ri = 0; ri < 4; ri++)
                qv[ri] = *(const float4*)&Qs[(ty * 4 + ri) * SD + d];
#pragma unroll
            for (int cj = 0; cj < 4; cj++)
                kv[cj] = *(const float4*)&Ks[(tx + cj * 16) * SD + d];
#pragma unroll
            for (int ri = 0; ri < 4; ri++)
#pragma unroll
                for (int cj = 0; cj < 4; cj++) {
                    s[ri][cj] = fmaf(qv[ri].x, kv[cj].x, s[ri][cj]);
                    s[ri][cj] = fmaf(qv[ri].y, kv[cj].y, s[ri][cj]);
                    s[ri][cj] = fmaf(qv[ri].z, kv[cj].z, s[ri][cj]);
                    s[ri][cj] = fmaf(qv[ri].w, kv[cj].w, s[ri][cj]);
                }
        }

        const bool diag = (kb == qb);
#pragma unroll
        for (int ri = 0; ri < 4; ri++) {
            const int gi = q0 + ty * 4 + ri;
#pragma unroll
            for (int cj = 0; cj < 4; cj++) {
                const int gj = k0 + tx + cj * 16;
                s[ri][cj] *= scale;
                if (diag && gj > gi) s[ri][cj] = -1e30f;
            }
        }

#pragma unroll
        for (int ri = 0; ri < 4; ri++) {
            float mx = fmaxf(fmaxf(s[ri][0], s[ri][1]), fmaxf(s[ri][2], s[ri][3]));
#pragma unroll
            for (int off = 8; off >= 1; off >>= 1)
                mx = fmaxf(mx, __shfl_xor_sync(0xffffffffu, mx, off));
            const float mnew = fmaxf(m[ri], mx);
            const float corr = __expf(m[ri] - mnew);
            float rs = 0.f;
            const int row = ty * 4 + ri;
#pragma unroll
            for (int cj = 0; cj < 4; cj++) {
                float p = __expf(s[ri][cj] - mnew);
                Ps[row * BKV + tx + cj * 16] = p;
                rs += p;
            }
#pragma unroll
            for (int off = 8; off >= 1; off >>= 1)
                rs += __shfl_xor_sync(0xffffffffu, rs, off);
            l[ri] = l[ri] * corr + rs;
            m[ri] = mnew;
#pragma unroll
            for (int dd = 0; dd < 8; dd++) acc[ri][dd] *= corr;
        }
        __syncwarp();

        for (int j = 0; j < BKV; j++) {
            float pv[4];
#pragma unroll
            for (int ri = 0; ri < 4; ri++) pv[ri] = Ps[(ty * 4 + ri) * BKV + j];
            float vv[8];
#pragma unroll
            for (int dd = 0; dd < 8; dd++) vv[dd] = Vs[j * SD + tx + dd * 16];
#pragma unroll
            for (int ri = 0; ri < 4; ri++)
#pragma unroll
                for (int dd = 0; dd < 8; dd++)
                    acc[ri][dd] = fmaf(pv[ri], vv[dd], acc[ri][dd]);
        }
        __syncthreads();
    }

#pragma unroll
    for (int ri = 0; ri < 4; ri++) {
        const int gi = q0 + ty * 4 + ri;
        const float inv = 1.0f / l[ri];
#pragma unroll
        for (int dd = 0; dd < 8; dd++) {
            o[(size_t)gi * HID + h * HD + tx + dd * 16] = acc[ri][dd] * inv;
        }
    }
}

// ---------------------------------------------------------------------------
// launcher
// ---------------------------------------------------------------------------
extern "C" void kernel_launch(void* const* d_in, const int* in_sizes, int n_in,
                              void* d_out, int out_size) {
    const float* hidden = (const float*)d_in[0];
    const float* cosb = (const float*)d_in[2];
    const float* sinb = (const float*)d_in[3];
    const float* wq = (const float*)d_in[4];
    const float* wk = (const float*)d_in[5];
    const float* wv = (const float*)d_in[6];
    const float* wo = (const float*)d_in[7];
    float* out = (float*)d_out;

    float *q, *k, *v, *attn;
    cudaGetSymbolAddress((void**)&q, g_q);
    cudaGetSymbolAddress((void**)&k, g_k);
    cudaGetSymbolAddress((void**)&v, g_v);
    cudaGetSymbolAddress((void**)&attn, g_attn);
    __nv_bfloat16 *hid_hi, *hid_lo, *wq_hi, *wq_lo, *wk_hi, *wk_lo;
    __nv_bfloat16 *wv_hi, *wv_lo, *wo_hi, *wo_lo, *at_hi, *at_lo;
    cudaGetSymbolAddress((void**)&hid_hi, g_hid_hi);
    cudaGetSymbolAddress((void**)&hid_lo, g_hid_lo);
    cudaGetSymbolAddress((void**)&wq_hi, g_wq_hi);
    cudaGetSymbolAddress((void**)&wq_lo, g_wq_lo);
    cudaGetSymbolAddress((void**)&wk_hi, g_wk_hi);
    cudaGetSymbolAddress((void**)&wk_lo, g_wk_lo);
    cudaGetSymbolAddress((void**)&wv_hi, g_wv_hi);
    cudaGetSymbolAddress((void**)&wv_lo, g_wv_lo);
    cudaGetSymbolAddress((void**)&wo_hi, g_wo_hi);
    cudaGetSymbolAddress((void**)&wo_lo, g_wo_lo);
    cudaGetSymbolAddress((void**)&at_hi, g_attn_hi);
    cudaGetSymbolAddress((void**)&at_lo, g_attn_lo);

    // splits
    {
        int n;
        n = S_LEN * HID;
        split_bf16<<<(n / 4 + 255) / 256, 256>>>(hidden, hid_hi, hid_lo, n);
        n = HID * HID;
        split_bf16<<<(n / 4 + 255) / 256, 256>>>(wq, wq_hi, wq_lo, n);
        n = KVDIM * HID;
        split_bf16<<<(n / 4 + 255) / 256, 256>>>(wk, wk_hi, wk_lo, n);
        split_bf16<<<(n / 4 + 255) / 256, 256>>>(wv, wv_hi, wv_lo, n);
        n = HID * HID;
        split_bf16<<<(n / 4 + 255) / 256, 256>>>(wo, wo_hi, wo_lo, n);
    }

    cudaFuncSetAttribute(gemm_bf16x3, cudaFuncAttributeMaxDynamicSharedMemorySize,
                         GEMM_SMEM);

    // QKV projections (bf16x3 tensor-core GEMM)
    gemm_bf16x3<<<dim3(HID / GBN, S_LEN / GBM), 256, GEMM_SMEM>>>(
        hid_hi, hid_lo, wq_hi, wq_lo, q, S_LEN, HID, HID);
    gemm_bf16x3<<<dim3(KVDIM / GBN, S_LEN / GBM), 256, GEMM_SMEM>>>(
        hid_hi, hid_lo, wk_hi, wk_lo, k, S_LEN, KVDIM, HID);
    gemm_bf16x3<<<dim3(KVDIM / GBN, S_LEN / GBM), 256, GEMM_SMEM>>>(
        hid_hi, hid_lo, wv_hi, wv_lo, v, S_LEN, KVDIM, HID);

    // RoPE
    {
        int total = S_LEN * (NH + NKV) * (HD / 2);
        rope_kernel<<<(total + 255) / 256, 256>>>(q, k, cosb, sinb);
    }

    // flash attention
    cudaFuncSetAttribute(flash_kernel, cudaFuncAttributeMaxDynamicSharedMemorySize,
                         FLASH_SMEM);
    flash_kernel<<<dim3(S_LEN / BQ, NH), 256, FLASH_SMEM>>>(q, k, v, attn);

    // split attn, then output projection
    {
        int n = S_LEN * HID;
        split_bf16<<<(n / 4 + 255) / 256, 256>>>(attn, at_hi, at_lo, n);
    }
    gemm_bf16x3<<<dim3(HID / GBN, S_LEN / GBM), 256, GEMM_SMEM>>>(
        at_hi, at_lo, wo_hi, wo_lo, out, S_LEN, HID, HID);
}

// round 3
// speedup vs baseline: 3.0237x; 1.3498x over previous
#include <cuda_runtime.h>
#include <cuda_bf16.h>
#include <stdint.h>

// ---------------------------------------------------------------------------
// LlamaAttention: S=2048, HID=4096, NH=32, NKV=8, D=128
// GEMMs + flash attention all on tensor cores via bf16x3 split.
// ---------------------------------------------------------------------------

#define S_LEN 2048
#define HID   4096
#define NH    32
#define NKV   8
#define HD    128
#define KVDIM (NKV * HD)   // 1024

// fp32 scratch
__device__ float g_q[S_LEN * HID];
__device__ float g_k[S_LEN * KVDIM];
__device__ float g_v[S_LEN * KVDIM];
__device__ float g_attn[S_LEN * HID];

// bf16 split scratch
__device__ __nv_bfloat16 g_hid_hi[S_LEN * HID];
__device__ __nv_bfloat16 g_hid_lo[S_LEN * HID];
__device__ __nv_bfloat16 g_wq_hi[HID * HID];
__device__ __nv_bfloat16 g_wq_lo[HID * HID];
__device__ __nv_bfloat16 g_wk_hi[KVDIM * HID];
__device__ __nv_bfloat16 g_wk_lo[KVDIM * HID];
__device__ __nv_bfloat16 g_wv_hi[KVDIM * HID];
__device__ __nv_bfloat16 g_wv_lo[KVDIM * HID];
__device__ __nv_bfloat16 g_wo_hi[HID * HID];
__device__ __nv_bfloat16 g_wo_lo[HID * HID];
__device__ __nv_bfloat16 g_attn_hi[S_LEN * HID];
__device__ __nv_bfloat16 g_attn_lo[S_LEN * HID];
// attention operands (bf16 hi/lo)
__device__ __nv_bfloat16 g_qr_hi[S_LEN * HID];
__device__ __nv_bfloat16 g_qr_lo[S_LEN * HID];
__device__ __nv_bfloat16 g_kr_hi[S_LEN * KVDIM];
__device__ __nv_bfloat16 g_kr_lo[S_LEN * KVDIM];
__device__ __nv_bfloat16 g_vt_hi[KVDIM * S_LEN];   // transposed [d][s]
__device__ __nv_bfloat16 g_vt_lo[KVDIM * S_LEN];

// ---------------------------------------------------------------------------
// split fp32 -> bf16 hi + lo residual
// ---------------------------------------------------------------------------
__global__ void split_bf16(const float* __restrict__ x,
                           __nv_bfloat16* __restrict__ hi,
                           __nv_bfloat16* __restrict__ lo, int n) {
    int i = (blockIdx.x * blockDim.x + threadIdx.x) * 4;
    if (i >= n) return;
    float4 f = *(const float4*)(x + i);
    __nv_bfloat16 h0 = __float2bfloat16(f.x);
    __nv_bfloat16 h1 = __float2bfloat16(f.y);
    __nv_bfloat16 h2 = __float2bfloat16(f.z);
    __nv_bfloat16 h3 = __float2bfloat16(f.w);
    __nv_bfloat16 l0 = __float2bfloat16(f.x - __bfloat162float(h0));
    __nv_bfloat16 l1 = __float2bfloat16(f.y - __bfloat162float(h1));
    __nv_bfloat16 l2 = __float2bfloat16(f.z - __bfloat162float(h2));
    __nv_bfloat16 l3 = __float2bfloat16(f.w - __bfloat162float(h3));
    ushort4 hv, lv;
    hv.x = *(unsigned short*)&h0; hv.y = *(unsigned short*)&h1;
    hv.z = *(unsigned short*)&h2; hv.w = *(unsigned short*)&h3;
    lv.x = *(unsigned short*)&l0; lv.y = *(unsigned short*)&l1;
    lv.z = *(unsigned short*)&l2; lv.w = *(unsigned short*)&l3;
    *(ushort4*)(hi + i) = hv;
    *(ushort4*)(lo + i) = lv;
}

// ---------------------------------------------------------------------------
// bf16x3 GEMM (3-stage cp.async): C = Ah·Bh^T + Ah·Bl^T + Al·Bh^T
// ---------------------------------------------------------------------------
#define GBM 128
#define GBN 128
#define GBK 32
#define LDT_B 80
#define TILE_B (128 * LDT_B)
#define STAGE_B (4 * TILE_B)
#define GEMM_SMEM (3 * STAGE_B)

__device__ __forceinline__ void ldsm_x4(uint32_t addr, uint32_t& r0, uint32_t& r1,
                                        uint32_t& r2, uint32_t& r3) {
    asm volatile("ldmatrix.sync.aligned.m8n8.x4.shared.b16 {%0,%1,%2,%3}, [%4];"
                 : "=r"(r0), "=r"(r1), "=r"(r2), "=r"(r3) : "r"(addr));
}

__device__ __forceinline__ void mma_bf16(float* c, const uint32_t* a, const uint32_t* b) {
    asm volatile(
        "mma.sync.aligned.m16n8k16.row.col.f32.bf16.bf16.f32 "
        "{%0,%1,%2,%3},{%4,%5,%6,%7},{%8,%9},{%0,%1,%2,%3};"
        : "+f"(c[0]), "+f"(c[1]), "+f"(c[2]), "+f"(c[3])
        : "r"(a[0]), "r"(a[1]), "r"(a[2]), "r"(a[3]), "r"(b[0]), "r"(b[1]));
}

__global__ __launch_bounds__(256, 1) void gemm_bf16x3(
    const __nv_bfloat16* __restrict__ Ah, const __nv_bfloat16* __restrict__ Al,
    const __nv_bfloat16* __restrict__ Bh, const __nv_bfloat16* __restrict__ Bl,
    float* __restrict__ C, int M, int N, int K) {
    extern __shared__ char smem[];
    const int tid = threadIdx.x;
    const int lane = tid & 31;
    const int warp = tid >> 5;
    const int wr = warp >> 2;
    const int wc = warp & 3;
    const int bm = blockIdx.y * GBM;
    const int bn = blockIdx.x * GBN;
    uint32_t sbase = (uint32_t)__cvta_generic_to_shared(smem);

    float acc[4][4][4];
#pragma unroll
    for (int mi = 0; mi < 4; mi++)
#pragma unroll
        for (int ni = 0; ni < 4; ni++)
#pragma unroll
            for (int t = 0; t < 4; t++) acc[mi][ni][t] = 0.f;

    const __nv_bfloat16* mats[4] = {Ah, Al, Bh, Bl};

    auto load_stage = [&](int s, int k0) {
#pragma unroll
        for (int i = 0; i < 8; i++) {
            int c = tid + i * 256;
            int mat = c >> 9;
            int row = (c >> 2) & 127;
            int ch = c & 3;
            int grow = (mat < 2 ? bm : bn) + row;
            const void* gptr = mats[mat] + (size_t)grow * K + k0 + ch * 8;
            uint32_t daddr = sbase + s * STAGE_B + mat * TILE_B + row * LDT_B + ch * 16;
            asm volatile("cp.async.cg.shared.global [%0], [%1], 16;"
                         :: "r"(daddr), "l"(gptr));
        }
        asm volatile("cp.async.commit_group;");
    };

    const int NIT = K / GBK;
    load_stage(0, 0);
    load_stage(1, GBK);

    for (int it = 0; it < NIT; it++) {
        asm volatile("cp.async.wait_group 1;");
        __syncthreads();
        if (it + 2 < NIT) load_stage((it + 2) % 3, (it + 2) * GBK);
        else              asm volatile("cp.async.commit_group;");

        uint32_t sa = sbase + (it % 3) * STAGE_B;
#pragma unroll
        for (int ks = 0; ks < 2; ks++) {
            uint32_t ah[4][4], al[4][4];
#pragma unroll
            for (int mi = 0; mi < 4; mi++) {
                uint32_t off = (uint32_t)((wr * 64 + mi * 16 + (lane & 15)) * LDT_B +
                                          ks * 32 + ((lane >> 4) & 1) * 16);
                ldsm_x4(sa + off, ah[mi][0], ah[mi][1], ah[mi][2], ah[mi][3]);
                ldsm_x4(sa + TILE_B + off, al[mi][0], al[mi][1], al[mi][2], al[mi][3]);
            }
            uint32_t bh[4][2], bl[4][2];
#pragma unroll
            for (int np = 0; np < 2; np++) {
                int brow = (lane & 7) + ((lane >> 4) << 3);
                int bch = (lane >> 3) & 1;
                uint32_t off = (uint32_t)((wc * 32 + np * 16 + brow) * LDT_B +
                                          ks * 32 + bch * 16);
                uint32_t r0, r1, r2, r3;
                ldsm_x4(sa + 2 * TILE_B + off, r0, r1, r2, r3);
                bh[np * 2][0] = r0; bh[np * 2][1] = r1;
                bh[np * 2 + 1][0] = r2; bh[np * 2 + 1][1] = r3;
                ldsm_x4(sa + 3 * TILE_B + off, r0, r1, r2, r3);
                bl[np * 2][0] = r0; bl[np * 2][1] = r1;
                bl[np * 2 + 1][0] = r2; bl[np * 2 + 1][1] = r3;
            }
#pragma unroll
            for (int mi = 0; mi < 4; mi++)
#pragma unroll
                for (int ni = 0; ni < 4; ni++) {
                    mma_bf16(acc[mi][ni], ah[mi], bh[ni]);
                    mma_bf16(acc[mi][ni], ah[mi], bl[ni]);
                    mma_bf16(acc[mi][ni], al[mi], bh[ni]);
                }
        }
        __syncthreads();
    }

#pragma unroll
    for (int mi = 0; mi < 4; mi++) {
        const int r0 = bm + wr * 64 + mi * 16 + (lane >> 2);
#pragma unroll
        for (int ni = 0; ni < 4; ni++) {
            const int col = bn + wc * 32 + ni * 8 + (lane & 3) * 2;
            *(float2*)&C[(size_t)r0 * N + col] = make_float2(acc[mi][ni][0], acc[mi][ni][1]);
            *(float2*)&C[(size_t)(r0 + 8) * N + col] = make_float2(acc[mi][ni][2], acc[mi][ni][3]);
        }
    }
}

// ---------------------------------------------------------------------------
// RoPE + split: fp32 q,k -> rotated bf16 hi/lo
// ---------------------------------------------------------------------------
__global__ void rope_split(const float* __restrict__ q, const float* __restrict__ k,
                           const float* __restrict__ cosb, const float* __restrict__ sinb,
                           __nv_bfloat16* __restrict__ qh, __nv_bfloat16* __restrict__ ql,
                           __nv_bfloat16* __restrict__ kh, __nv_bfloat16* __restrict__ kl) {
    int idx = blockIdx.x * blockDim.x + threadIdx.x;
    const int total = S_LEN * (NH + NKV) * (HD / 2);
    if (idx >= total) return;
    int i = idx & 63;
    int h = (idx >> 6) % (NH + NKV);
    int s = idx / (64 * (NH + NKV));
    float c  = cosb[s * 64 + i];
    float sn = sinb[s * 64 + i];
    const float* base;
    __nv_bfloat16 *oh, *ol;
    if (h < NH) {
        size_t off = (size_t)s * HID + h * HD;
        base = q + off; oh = qh + off; ol = ql + off;
    } else {
        size_t off = (size_t)s * KVDIM + (h - NH) * HD;
        base = k + off; oh = kh + off; ol = kl + off;
    }
    float a = base[2 * i];
    float b = base[2 * i + 1];
    float x = a * c - b * sn;
    float y = a * sn + b * c;
    __nv_bfloat162 hv = __floats2bfloat162_rn(x, y);
    float rx = x - __bfloat162float(hv.x);
    float ry = y - __bfloat162float(hv.y);
    __nv_bfloat162 lv = __floats2bfloat162_rn(rx, ry);
    *(__nv_bfloat162*)(oh + 2 * i) = hv;
    *(__nv_bfloat162*)(ol + 2 * i) = lv;
}

// ---------------------------------------------------------------------------
// transpose + split: v[S,1024] fp32 -> vT hi/lo [1024, S] bf16
// ---------------------------------------------------------------------------
__global__ void transpose_split(const float* __restrict__ v,
                                __nv_bfloat16* __restrict__ th,
                                __nv_bfloat16* __restrict__ tl) {
    __shared__ float tile[32][33];
    const int bs = blockIdx.x * 32;   // s
    const int bd = blockIdx.y * 32;   // d
    const int tx = threadIdx.x;       // 0..31
    const int ty = threadIdx.y;       // 0..7
#pragma unroll
    for (int i = 0; i < 4; i++) {
        int sy = ty * 4 + i;
        tile[sy][tx] = v[(size_t)(bs + sy) * KVDIM + bd + tx];
    }
    __syncthreads();
#pragma unroll
    for (int i = 0; i < 4; i++) {
        int dy = ty * 4 + i;
        float val = tile[tx][dy];
        __nv_bfloat16 h = __float2bfloat16(val);
        __nv_bfloat16 l = __float2bfloat16(val - __bfloat162float(h));
        th[(size_t)(bd + dy) * S_LEN + bs + tx] = h;
        tl[(size_t)(bd + dy) * S_LEN + bs + tx] = l;
    }
}

// ---------------------------------------------------------------------------
// Tensor-core causal flash attention (bf16x3). Grid (32 qb, 32 h), 128 thr.
// BQ=BKV=64, D=128. Warp w owns Q rows 16w..16w+15.
// ---------------------------------------------------------------------------
#define QLDT 272
#define VLDT 144
#define OFF_QH 0
#define OFF_QL (OFF_QH + 64 * QLDT)
#define OFF_KH (OFF_QL + 64 * QLDT)
#define OFF_KL (OFF_KH + 64 * QLDT)
#define OFF_VH (OFF_KL + 64 * QLDT)
#define OFF_VL (OFF_VH + 128 * VLDT)
#define FLASH_SMEM (OFF_VL + 128 * VLDT)   // 106496 bytes

__device__ __forceinline__ uint32_t pack_hl(float f0, float f1, uint32_t& lo) {
    __nv_bfloat162 h = __floats2bfloat162_rn(f0, f1);
    float r0 = f0 - __bfloat162float(h.x);
    float r1 = f1 - __bfloat162float(h.y);
    __nv_bfloat162 l = __floats2bfloat162_rn(r0, r1);
    lo = *(uint32_t*)&l;
    return *(uint32_t*)&h;
}

__global__ __launch_bounds__(128, 1) void flash_tc(
    const __nv_bfloat16* __restrict__ qh, const __nv_bfloat16* __restrict__ ql,
    const __nv_bfloat16* __restrict__ kh, const __nv_bfloat16* __restrict__ kl,
    const __nv_bfloat16* __restrict__ vth, const __nv_bfloat16* __restrict__ vtl,
    float* __restrict__ o) {
    extern __shared__ char sm[];
    const int qb = blockIdx.x;
    const int h  = blockIdx.y;
    const int kvh = h >> 2;
    const int tid = threadIdx.x;
    const int lane = tid & 31;
    const int w = tid >> 5;
    const int q0 = qb * 64;
    const float scale = 0.08838834764831845f;
    uint32_t sb = (uint32_t)__cvta_generic_to_shared(sm);

    const int brow = (lane & 7) + ((lane >> 4) << 3);
    const int bch = (lane >> 3) & 1;

    // load Q tiles (hi, lo): 64 rows x 128 bf16
    for (int i = tid; i < 2048; i += 128) {
        int mat = i >> 10;
        int idx = i & 1023;
        int r = idx >> 4;
        int c = idx & 15;
        const __nv_bfloat16* src = (mat ? ql : qh) + (size_t)(q0 + r) * HID + h * HD + c * 8;
        *(uint4*)(sm + (mat ? OFF_QL : OFF_QH) + r * QLDT + c * 16) = *(const uint4*)src;
    }

    float m0 = -1e30f, m1 = -1e30f, l0 = 0.f, l1 = 0.f;
    float oa[16][4];
#pragma unroll
    for (int i = 0; i < 16; i++)
#pragma unroll
        for (int t = 0; t < 4; t++) oa[i][t] = 0.f;

    const int r0g = q0 + w * 16 + (lane >> 2);
    const int r1g = r0g + 8;

    for (int kb = 0; kb <= qb; kb++) {
        const int k0 = kb * 64;
        __syncthreads();
        // load K tiles
        for (int i = tid; i < 2048; i += 128) {
            int mat = i >> 10;
            int idx = i & 1023;
            int r = idx >> 4;
            int c = idx & 15;
            const __nv_bfloat16* src = (mat ? kl : kh) + (size_t)(k0 + r) * KVDIM + kvh * HD + c * 8;
            *(uint4*)(sm + (mat ? OFF_KL : OFF_KH) + r * QLDT + c * 16) = *(const uint4*)src;
        }
        // load V tiles (transposed: 128 d-rows x 64 kv)
        for (int i = tid; i < 2048; i += 128) {
            int mat = i >> 10;
            int idx = i & 1023;
            int r = idx >> 3;
            int c = idx & 7;
            const __nv_bfloat16* src = (mat ? vtl : vth) + (size_t)(kvh * HD + r) * S_LEN + k0 + c * 8;
            *(uint4*)(sm + (mat ? OFF_VL : OFF_VH) + r * VLDT + c * 16) = *(const uint4*)src;
        }
        __syncthreads();

        // S = Q K^T (bf16x3)
        float s[8][4];
#pragma unroll
        for (int nf = 0; nf < 8; nf++)
#pragma unroll
            for (int t = 0; t < 4; t++) s[nf][t] = 0.f;

#pragma unroll
        for (int kf = 0; kf < 8; kf++) {
            uint32_t aoff = (uint32_t)((w * 16 + (lane & 15)) * QLDT + kf * 32 + (lane >> 4) * 16);
            uint32_t ah[4], al[4];
            ldsm_x4(sb + OFF_QH + aoff, ah[0], ah[1], ah[2], ah[3]);
            ldsm_x4(sb + OFF_QL + aoff, al[0], al[1], al[2], al[3]);
#pragma unroll
            for (int np = 0; np < 4; np++) {
                uint32_t boff = (uint32_t)((np * 16 + brow) * QLDT + kf * 32 + bch * 16);
                uint32_t bh[4], bl[4];
                ldsm_x4(sb + OFF_KH + boff, bh[0], bh[1], bh[2], bh[3]);
                ldsm_x4(sb + OFF_KL + boff, bl[0], bl[1], bl[2], bl[3]);
                mma_bf16(s[np * 2], ah, bh);
                mma_bf16(s[np * 2], ah, bl);
                mma_bf16(s[np * 2], al, bh);
                mma_bf16(s[np * 2 + 1], ah, bh + 2);
                mma_bf16(s[np * 2 + 1], ah, bl + 2);
                mma_bf16(s[np * 2 + 1], al, bh + 2);
            }
        }

        // scale + causal mask
#pragma unroll
        for (int nf = 0; nf < 8; nf++)
#pragma unroll
            for (int t = 0; t < 4; t++) s[nf][t] *= scale;
        if (kb == qb) {
#pragma unroll
            for (int nf = 0; nf < 8; nf++) {
                int cg = k0 + nf * 8 + (lane & 3) * 2;
                if (cg > r0g)     s[nf][0] = -1e30f;
                if (cg + 1 > r0g) s[nf][1] = -1e30f;
                if (cg > r1g)     s[nf][2] = -1e30f;
                if (cg + 1 > r1g) s[nf][3] = -1e30f;
            }
        }

        // online softmax
        float mx0 = -1e30f, mx1 = -1e30f;
#pragma unroll
        for (int nf = 0; nf < 8; nf++) {
            mx0 = fmaxf(mx0, fmaxf(s[nf][0], s[nf][1]));
            mx1 = fmaxf(mx1, fmaxf(s[nf][2], s[nf][3]));
        }
        mx0 = fmaxf(mx0, __shfl_xor_sync(0xffffffffu, mx0, 1));
        mx0 = fmaxf(mx0, __shfl_xor_sync(0xffffffffu, mx0, 2));
        mx1 = fmaxf(mx1, __shfl_xor_sync(0xffffffffu, mx1, 1));
        mx1 = fmaxf(mx1, __shfl_xor_sync(0xffffffffu, mx1, 2));
        float mn0 = fmaxf(m0, mx0);
        float mn1 = fmaxf(m1, mx1);
        float c0 = __expf(m0 - mn0);
        float c1 = __expf(m1 - mn1);
        m0 = mn0; m1 = mn1;
        float rs0 = 0.f, rs1 = 0.f;
#pragma unroll
        for (int nf = 0; nf < 8; nf++) {
            s[nf][0] = __expf(s[nf][0] - m0); rs0 += s[nf][0];
            s[nf][1] = __expf(s[nf][1] - m0); rs0 += s[nf][1];
            s[nf][2] = __expf(s[nf][2] - m1); rs1 += s[nf][2];
            s[nf][3] = __expf(s[nf][3] - m1); rs1 += s[nf][3];
        }
        rs0 += __shfl_xor_sync(0xffffffffu, rs0, 1);
        rs0 += __shfl_xor_sync(0xffffffffu, rs0, 2);
        rs1 += __shfl_xor_sync(0xffffffffu, rs1, 1);
        rs1 += __shfl_xor_sync(0xffffffffu, rs1, 2);
        l0 = l0 * c0 + rs0;
        l1 = l1 * c1 + rs1;
#pragma unroll
        for (int i = 0; i < 16; i++) {
            oa[i][0] *= c0; oa[i][1] *= c0;
            oa[i][2] *= c1; oa[i][3] *= c1;
        }

        // convert P to bf16 hi/lo fragments (register-only)
        uint32_t ph[8][2], pl[8][2];
#pragma unroll
        for (int nf = 0; nf < 8; nf++) {
            ph[nf][0] = pack_hl(s[nf][0], s[nf][1], pl[nf][0]);
            ph[nf][1] = pack_hl(s[nf][2], s[nf][3], pl[nf][1]);
        }

        // O += P V (bf16x3)
#pragma unroll
        for (int kf2 = 0; kf2 < 4; kf2++) {
            uint32_t pah[4] = {ph[2 * kf2][0], ph[2 * kf2][1],
                               ph[2 * kf2 + 1][0], ph[2 * kf2 + 1][1]};
            uint32_t pal[4] = {pl[2 * kf2][0], pl[2 * kf2][1],
                               pl[2 * kf2 + 1][0], pl[2 * kf2 + 1][1]};
#pragma unroll
            for (int np = 0; np < 8; np++) {
                uint32_t voff = (uint32_t)((np * 16 + brow) * VLDT + kf2 * 32 + bch * 16);
                uint32_t vh[4], vl[4];
                ldsm_x4(sb + OFF_VH + voff, vh[0], vh[1], vh[2], vh[3]);
                ldsm_x4(sb + OFF_VL + voff, vl[0], vl[1], vl[2], vl[3]);
                mma_bf16(oa[np * 2], pah, vh);
                mma_bf16(oa[np * 2], pah, vl);
                mma_bf16(oa[np * 2], pal, vh);
                mma_bf16(oa[np * 2 + 1], pah, vh + 2);
                mma_bf16(oa[np * 2 + 1], pah, vl + 2);
                mma_bf16(oa[np * 2 + 1], pal, vh + 2);
            }
        }
    }

    // epilogue
    const float inv0 = 1.0f / l0;
    const float inv1 = 1.0f / l1;
#pragma unroll
    for (int nf2 = 0; nf2 < 16; nf2++) {
        int col = h * HD + nf2 * 8 + (lane & 3) * 2;
        *(float2*)&o[(size_t)r0g * HID + col] = make_float2(oa[nf2][0] * inv0, oa[nf2][1] * inv0);
        *(float2*)&o[(size_t)r1g * HID + col] = make_float2(oa[nf2][2] * inv1, oa[nf2][3] * inv1);
    }
}

// ---------------------------------------------------------------------------
// launcher
// ---------------------------------------------------------------------------
extern "C" void kernel_launch(void* const* d_in, const int* in_sizes, int n_in,
                              void* d_out, int out_size) {
    const float* hidden = (const float*)d_in[0];
    const float* cosb = (const float*)d_in[2];
    const float* sinb = (const float*)d_in[3];
    const float* wq = (const float*)d_in[4];
    const float* wk = (const float*)d_in[5];
    const float* wv = (const float*)d_in[6];
    const float* wo = (const float*)d_in[7];
    float* out = (float*)d_out;

    float *q, *k, *v, *attn;
    cudaGetSymbolAddress((void**)&q, g_q);
    cudaGetSymbolAddress((void**)&k, g_k);
    cudaGetSymbolAddress((void**)&v, g_v);
    cudaGetSymbolAddress((void**)&attn, g_attn);
    __nv_bfloat16 *hid_hi, *hid_lo, *wq_hi, *wq_lo, *wk_hi, *wk_lo;
    __nv_bfloat16 *wv_hi, *wv_lo, *wo_hi, *wo_lo, *at_hi, *at_lo;
    __nv_bfloat16 *qr_hi, *qr_lo, *kr_hi, *kr_lo, *vt_hi, *vt_lo;
    cudaGetSymbolAddress((void**)&hid_hi, g_hid_hi);
    cudaGetSymbolAddress((void**)&hid_lo, g_hid_lo);
    cudaGetSymbolAddress((void**)&wq_hi, g_wq_hi);
    cudaGetSymbolAddress((void**)&wq_lo, g_wq_lo);
    cudaGetSymbolAddress((void**)&wk_hi, g_wk_hi);
    cudaGetSymbolAddress((void**)&wk_lo, g_wk_lo);
    cudaGetSymbolAddress((void**)&wv_hi, g_wv_hi);
    cudaGetSymbolAddress((void**)&wv_lo, g_wv_lo);
    cudaGetSymbolAddress((void**)&wo_hi, g_wo_hi);
    cudaGetSymbolAddress((void**)&wo_lo, g_wo_lo);
    cudaGetSymbolAddress((void**)&at_hi, g_attn_hi);
    cudaGetSymbolAddress((void**)&at_lo, g_attn_lo);
    cudaGetSymbolAddress((void**)&qr_hi, g_qr_hi);
    cudaGetSymbolAddress((void**)&qr_lo, g_qr_lo);
    cudaGetSymbolAddress((void**)&kr_hi, g_kr_hi);
    cudaGetSymbolAddress((void**)&kr_lo, g_kr_lo);
    cudaGetSymbolAddress((void**)&vt_hi, g_vt_hi);
    cudaGetSymbolAddress((void**)&vt_lo, g_vt_lo);

    // splits
    {
        int n;
        n = S_LEN * HID;
        split_bf16<<<(n / 4 + 255) / 256, 256>>>(hidden, hid_hi, hid_lo, n);
        n = HID * HID;
        split_bf16<<<(n / 4 + 255) / 256, 256>>>(wq, wq_hi, wq_lo, n);
        n = KVDIM * HID;
        split_bf16<<<(n / 4 + 255) / 256, 256>>>(wk, wk_hi, wk_lo, n);
        split_bf16<<<(n / 4 + 255) / 256, 256>>>(wv, wv_hi, wv_lo, n);
        n = HID * HID;
        split_bf16<<<(n / 4 + 255) / 256, 256>>>(wo, wo_hi, wo_lo, n);
    }

    cudaFuncSetAttribute(gemm_bf16x3, cudaFuncAttributeMaxDynamicSharedMemorySize,
                         GEMM_SMEM);

    // QKV projections
    gemm_bf16x3<<<dim3(HID / GBN, S_LEN / GBM), 256, GEMM_SMEM>>>(
        hid_hi, hid_lo, wq_hi, wq_lo, q, S_LEN, HID, HID);
    gemm_bf16x3<<<dim3(KVDIM / GBN, S_LEN / GBM), 256, GEMM_SMEM>>>(
        hid_hi, hid_lo, wk_hi, wk_lo, k, S_LEN, KVDIM, HID);
    gemm_bf16x3<<<dim3(KVDIM / GBN, S_LEN / GBM), 256, GEMM_SMEM>>>(
        hid_hi, hid_lo, wv_hi, wv_lo, v, S_LEN, KVDIM, HID);

    // RoPE + split, V transpose + split
    {
        int total = S_LEN * (NH + NKV) * (HD / 2);
        rope_split<<<(total + 255) / 256, 256>>>(q, k, cosb, sinb,
                                                 qr_hi, qr_lo, kr_hi, kr_lo);
        transpose_split<<<dim3(S_LEN / 32, KVDIM / 32), dim3(32, 8)>>>(v, vt_hi, vt_lo);
    }

    // tensor-core flash attention
    cudaFuncSetAttribute(flash_tc, cudaFuncAttributeMaxDynamicSharedMemorySize,
                         FLASH_SMEM);
    flash_tc<<<dim3(32, 32), 128, FLASH_SMEM>>>(qr_hi, qr_lo, kr_hi, kr_lo,
                                                vt_hi, vt_lo, attn);

    // split attn, output projection
    {
        int n = S_LEN * HID;
        split_bf16<<<(n / 4 + 255) / 256, 256>>>(attn, at_hi, at_lo, n);
    }
    gemm_bf16x3<<<dim3(HID / GBN, S_LEN / GBM), 256, GEMM_SMEM>>>(
        at_hi, at_lo, wo_hi, wo_lo, out, S_LEN, HID, HID);
}

// round 5
// speedup vs baseline: 3.1866x; 1.0539x over previous
#include <cuda_runtime.h>
#include <cuda_bf16.h>
#include <stdint.h>

// ---------------------------------------------------------------------------
// LlamaAttention: S=2048, HID=4096, NH=32, NKV=8, D=128
// All matmuls on tensor cores (warp mma.sync, bf16x3 split for fp32 accuracy).
// NOTE: tcgen05 is NOT available (harness PTX target = compute_103, no 'a').
// ---------------------------------------------------------------------------

#define S_LEN 2048
#define HID   4096
#define NH    32
#define NKV   8
#define HD    128
#define KVDIM (NKV * HD)   // 1024

// fp32 scratch
__device__ float g_q[S_LEN * HID];
__device__ float g_k[S_LEN * KVDIM];
__device__ float g_v[S_LEN * KVDIM];

// bf16 split scratch
__device__ __nv_bfloat16 g_hid_hi[S_LEN * HID];
__device__ __nv_bfloat16 g_hid_lo[S_LEN * HID];
__device__ __nv_bfloat16 g_wq_hi[HID * HID];
__device__ __nv_bfloat16 g_wq_lo[HID * HID];
__device__ __nv_bfloat16 g_wk_hi[KVDIM * HID];
__device__ __nv_bfloat16 g_wk_lo[KVDIM * HID];
__device__ __nv_bfloat16 g_wv_hi[KVDIM * HID];
__device__ __nv_bfloat16 g_wv_lo[KVDIM * HID];
__device__ __nv_bfloat16 g_wo_hi[HID * HID];
__device__ __nv_bfloat16 g_wo_lo[HID * HID];
__device__ __nv_bfloat16 g_attn_hi[S_LEN * HID];
__device__ __nv_bfloat16 g_attn_lo[S_LEN * HID];
// attention operands
__device__ __nv_bfloat16 g_qr_hi[S_LEN * HID];
__device__ __nv_bfloat16 g_qr_lo[S_LEN * HID];
__device__ __nv_bfloat16 g_kr_hi[S_LEN * KVDIM];
__device__ __nv_bfloat16 g_kr_lo[S_LEN * KVDIM];
__device__ __nv_bfloat16 g_vt_hi[KVDIM * S_LEN];
__device__ __nv_bfloat16 g_vt_lo[KVDIM * S_LEN];

// ---------------------------------------------------------------------------
// split fp32 -> bf16 hi + lo residual (16 elems/thread for MLP)
// ---------------------------------------------------------------------------
__global__ void split_bf16(const float* __restrict__ x,
                           __nv_bfloat16* __restrict__ hi,
                           __nv_bfloat16* __restrict__ lo, int n) {
    int base = (blockIdx.x * blockDim.x + threadIdx.x) * 16;
    if (base >= n) return;
    float4 f[4];
#pragma unroll
    for (int j = 0; j < 4; j++) f[j] = *(const float4*)(x + base + j * 4);
#pragma unroll
    for (int j = 0; j < 4; j++) {
        __nv_bfloat16 h0 = __float2bfloat16(f[j].x);
        __nv_bfloat16 h1 = __float2bfloat16(f[j].y);
        __nv_bfloat16 h2 = __float2bfloat16(f[j].z);
        __nv_bfloat16 h3 = __float2bfloat16(f[j].w);
        __nv_bfloat16 l0 = __float2bfloat16(f[j].x - __bfloat162float(h0));
        __nv_bfloat16 l1 = __float2bfloat16(f[j].y - __bfloat162float(h1));
        __nv_bfloat16 l2 = __float2bfloat16(f[j].z - __bfloat162float(h2));
        __nv_bfloat16 l3 = __float2bfloat16(f[j].w - __bfloat162float(h3));
        ushort4 hv, lv;
        hv.x = *(unsigned short*)&h0; hv.y = *(unsigned short*)&h1;
        hv.z = *(unsigned short*)&h2; hv.w = *(unsigned short*)&h3;
        lv.x = *(unsigned short*)&l0; lv.y = *(unsigned short*)&l1;
        lv.z = *(unsigned short*)&l2; lv.w = *(unsigned short*)&l3;
        *(ushort4*)(hi + base + j * 4) = hv;
        *(ushort4*)(lo + base + j * 4) = lv;
    }
}

// ---------------------------------------------------------------------------
// warp-MMA primitives
// ---------------------------------------------------------------------------
__device__ __forceinline__ void ldsm_x4(uint32_t addr, uint32_t& r0, uint32_t& r1,
                                        uint32_t& r2, uint32_t& r3) {
    asm volatile("ldmatrix.sync.aligned.m8n8.x4.shared.b16 {%0,%1,%2,%3}, [%4];"
                 : "=r"(r0), "=r"(r1), "=r"(r2), "=r"(r3) : "r"(addr));
}

__device__ __forceinline__ void mma_bf16(float* c, const uint32_t* a, const uint32_t* b) {
    asm volatile(
        "mma.sync.aligned.m16n8k16.row.col.f32.bf16.bf16.f32 "
        "{%0,%1,%2,%3},{%4,%5,%6,%7},{%8,%9},{%0,%1,%2,%3};"
        : "+f"(c[0]), "+f"(c[1]), "+f"(c[2]), "+f"(c[3])
        : "r"(a[0]), "r"(a[1]), "r"(a[2]), "r"(a[3]), "r"(b[0]), "r"(b[1]));
}

// ---------------------------------------------------------------------------
// bf16x3 GEMM body: C[*,N] tile (bm,bn) = Ah·Bh^T + Ah·Bl^T + Al·Bh^T
// BM=BN=128, BK=64, 256 threads, 3-stage cp.async ring, 144B-padded rows.
// ---------------------------------------------------------------------------
#define GBK 64
#define LDT_B 144                      // 128B row + 16B pad (conflict-free LDSM)
#define TILE_B (128 * LDT_B)           // 18432
#define STAGE_B (4 * TILE_B)           // Ah, Al, Bh, Bl = 73728
#define GEMM_SMEM (3 * STAGE_B)        // 221184

__device__ __forceinline__ void gemm_body(
    const __nv_bfloat16* __restrict__ Ah, const __nv_bfloat16* __restrict__ Al,
    const __nv_bfloat16* __restrict__ Bh, const __nv_bfloat16* __restrict__ Bl,
    float* __restrict__ C, int N, int K, int bm, int bn, char* smem) {
    const int tid = threadIdx.x;
    const int lane = tid & 31;
    const int warp = tid >> 5;
    const int wr = warp >> 2;       // 0..1
    const int wc = warp & 3;        // 0..3
    uint32_t sbase = (uint32_t)__cvta_generic_to_shared(smem);

    float acc[4][4][4];
#pragma unroll
    for (int mi = 0; mi < 4; mi++)
#pragma unroll
        for (int ni = 0; ni < 4; ni++)
#pragma unroll
            for (int t = 0; t < 4; t++) acc[mi][ni][t] = 0.f;

    const __nv_bfloat16* mats[4] = {Ah, Al, Bh, Bl};

    auto load_stage = [&](int s, int it) {
        int kbase = it * GBK;
#pragma unroll
        for (int i = 0; i < 16; i++) {
            int c = tid + i * 256;
            int mat = c >> 10;
            int idx = c & 1023;
            int row = idx >> 3;
            int ch = idx & 7;
            int grow = (mat < 2 ? bm : bn) + row;
            const void* gptr = mats[mat] + (size_t)grow * K + kbase + ch * 8;
            uint32_t daddr = sbase + s * STAGE_B + mat * TILE_B + row * LDT_B + ch * 16;
            asm volatile("cp.async.cg.shared.global [%0], [%1], 16;"
                         :: "r"(daddr), "l"(gptr));
        }
        asm volatile("cp.async.commit_group;");
    };

    const int NIT = K / GBK;
    load_stage(0, 0);
    load_stage(1, 1);

    for (int it = 0; it < NIT; it++) {
        asm volatile("cp.async.wait_group 1;");
        __syncthreads();
        if (it + 2 < NIT) load_stage((it + 2) % 3, it + 2);
        else              asm volatile("cp.async.commit_group;");

        uint32_t sa = sbase + (it % 3) * STAGE_B;
#pragma unroll
        for (int ks = 0; ks < 4; ks++) {
            uint32_t ah[4][4], al[4][4];
#pragma unroll
            for (int mi = 0; mi < 4; mi++) {
                uint32_t off = (uint32_t)((wr * 64 + mi * 16 + (lane & 15)) * LDT_B +
                                          ks * 32 + ((lane >> 4) & 1) * 16);
                ldsm_x4(sa + off, ah[mi][0], ah[mi][1], ah[mi][2], ah[mi][3]);
                ldsm_x4(sa + TILE_B + off, al[mi][0], al[mi][1], al[mi][2], al[mi][3]);
            }
            uint32_t bh[4][2], bl[4][2];
#pragma unroll
            for (int np = 0; np < 2; np++) {
                int brow = (lane & 7) + ((lane >> 4) << 3);
                int bch = (lane >> 3) & 1;
                uint32_t off = (uint32_t)((wc * 32 + np * 16 + brow) * LDT_B +
                                          ks * 32 + bch * 16);
                uint32_t r0, r1, r2, r3;
                ldsm_x4(sa + 2 * TILE_B + off, r0, r1, r2, r3);
                bh[np * 2][0] = r0; bh[np * 2][1] = r1;
                bh[np * 2 + 1][0] = r2; bh[np * 2 + 1][1] = r3;
                ldsm_x4(sa + 3 * TILE_B + off, r0, r1, r2, r3);
                bl[np * 2][0] = r0; bl[np * 2][1] = r1;
                bl[np * 2 + 1][0] = r2; bl[np * 2 + 1][1] = r3;
            }
#pragma unroll
            for (int mi = 0; mi < 4; mi++)
#pragma unroll
                for (int ni = 0; ni < 4; ni++) {
                    mma_bf16(acc[mi][ni], ah[mi], bh[ni]);
                    mma_bf16(acc[mi][ni], ah[mi], bl[ni]);
                    mma_bf16(acc[mi][ni], al[mi], bh[ni]);
                }
        }
        __syncthreads();
    }

#pragma unroll
    for (int mi = 0; mi < 4; mi++) {
        const int r0 = bm + wr * 64 + mi * 16 + (lane >> 2);
#pragma unroll
        for (int ni = 0; ni < 4; ni++) {
            const int col = bn + wc * 32 + ni * 8 + (lane & 3) * 2;
            *(float2*)&C[(size_t)r0 * N + col] = make_float2(acc[mi][ni][0], acc[mi][ni][1]);
            *(float2*)&C[(size_t)(r0 + 8) * N + col] = make_float2(acc[mi][ni][2], acc[mi][ni][3]);
        }
    }
}

__global__ __launch_bounds__(256, 1) void gemm_main(
    const __nv_bfloat16* __restrict__ Ah, const __nv_bfloat16* __restrict__ Al,
    const __nv_bfloat16* __restrict__ Bh, const __nv_bfloat16* __restrict__ Bl,
    float* __restrict__ C, int N, int K) {
    extern __shared__ char smem[];
    gemm_body(Ah, Al, Bh, Bl, C, N, K, blockIdx.x * 128, blockIdx.y * 128, smem);
}

// K and V projections batched in one launch (blockIdx.z selects)
__global__ __launch_bounds__(256, 1) void gemm_kv(
    const __nv_bfloat16* __restrict__ Ah, const __nv_bfloat16* __restrict__ Al) {
    extern __shared__ char smem[];
    const __nv_bfloat16 *Bh, *Bl;
    float* C;
    if (blockIdx.z == 0) { Bh = g_wk_hi; Bl = g_wk_lo; C = g_k; }
    else                 { Bh = g_wv_hi; Bl = g_wv_lo; C = g_v; }
    gemm_body(Ah, Al, Bh, Bl, C, KVDIM, HID, blockIdx.x * 128, blockIdx.y * 128, smem);
}

// ---------------------------------------------------------------------------
// RoPE + split
// ---------------------------------------------------------------------------
__global__ void rope_split(const float* __restrict__ q, const float* __restrict__ k,
                           const float* __restrict__ cosb, const float* __restrict__ sinb,
                           __nv_bfloat16* __restrict__ qh, __nv_bfloat16* __restrict__ ql,
                           __nv_bfloat16* __restrict__ kh, __nv_bfloat16* __restrict__ kl) {
    int idx = blockIdx.x * blockDim.x + threadIdx.x;
    const int total = S_LEN * (NH + NKV) * (HD / 2);
    if (idx >= total) return;
    int i = idx & 63;
    int h = (idx >> 6) % (NH + NKV);
    int s = idx / (64 * (NH + NKV));
    float c  = cosb[s * 64 + i];
    float sn = sinb[s * 64 + i];
    const float* base;
    __nv_bfloat16 *oh, *ol;
    if (h < NH) {
        size_t off = (size_t)s * HID + h * HD;
        base = q + off; oh = qh + off; ol = ql + off;
    } else {
        size_t off = (size_t)s * KVDIM + (h - NH) * HD;
        base = k + off; oh = kh + off; ol = kl + off;
    }
    float a = base[2 * i];
    float b = base[2 * i + 1];
    float x = a * c - b * sn;
    float y = a * sn + b * c;
    __nv_bfloat162 hv = __floats2bfloat162_rn(x, y);
    float rx = x - __bfloat162float(hv.x);
    float ry = y - __bfloat162float(hv.y);
    __nv_bfloat162 lv = __floats2bfloat162_rn(rx, ry);
    *(__nv_bfloat162*)(oh + 2 * i) = hv;
    *(__nv_bfloat162*)(ol + 2 * i) = lv;
}

// ---------------------------------------------------------------------------
// transpose + split: v[S,1024] fp32 -> vT hi/lo [1024, S]
// ---------------------------------------------------------------------------
__global__ void transpose_split(const float* __restrict__ v,
                                __nv_bfloat16* __restrict__ th,
                                __nv_bfloat16* __restrict__ tl) {
    __shared__ float tile[32][33];
    const int bs = blockIdx.x * 32;
    const int bd = blockIdx.y * 32;
    const int tx = threadIdx.x;
    const int ty = threadIdx.y;
#pragma unroll
    for (int i = 0; i < 4; i++) {
        int sy = ty * 4 + i;
        tile[sy][tx] = v[(size_t)(bs + sy) * KVDIM + bd + tx];
    }
    __syncthreads();
#pragma unroll
    for (int i = 0; i < 4; i++) {
        int dy = ty * 4 + i;
        float val = tile[tx][dy];
        __nv_bfloat16 h = __float2bfloat16(val);
        __nv_bfloat16 l = __float2bfloat16(val - __bfloat162float(h));
        th[(size_t)(bd + dy) * S_LEN + bs + tx] = h;
        tl[(size_t)(bd + dy) * S_LEN + bs + tx] = l;
    }
}

// ---------------------------------------------------------------------------
// Tensor-core causal flash attention (bf16x3). Grid (32 qb, 32 h), 128 thr.
// qb reversed so longest blocks launch first. Output: bf16 hi/lo (fused split).
// ---------------------------------------------------------------------------
#define QLDT 272
#define VLDT 144
#define OFF_QH 0
#define OFF_QL (OFF_QH + 64 * QLDT)
#define OFF_KH (OFF_QL + 64 * QLDT)
#define OFF_KL (OFF_KH + 64 * QLDT)
#define OFF_VH (OFF_KL + 64 * QLDT)
#define OFF_VL (OFF_VH + 128 * VLDT)
#define FLASH_SMEM (OFF_VL + 128 * VLDT)

__device__ __forceinline__ uint32_t pack_hl(float f0, float f1, uint32_t& lo) {
    __nv_bfloat162 h = __floats2bfloat162_rn(f0, f1);
    float r0 = f0 - __bfloat162float(h.x);
    float r1 = f1 - __bfloat162float(h.y);
    __nv_bfloat162 l = __floats2bfloat162_rn(r0, r1);
    lo = *(uint32_t*)&l;
    return *(uint32_t*)&h;
}

__global__ __launch_bounds__(128, 1) void flash_tc(
    const __nv_bfloat16* __restrict__ qh, const __nv_bfloat16* __restrict__ ql,
    const __nv_bfloat16* __restrict__ kh, const __nv_bfloat16* __restrict__ kl,
    const __nv_bfloat16* __restrict__ vth, const __nv_bfloat16* __restrict__ vtl,
    __nv_bfloat16* __restrict__ ohi, __nv_bfloat16* __restrict__ olo) {
    extern __shared__ char sm[];
    const int qb = (int)gridDim.x - 1 - (int)blockIdx.x;   // longest first
    const int h  = blockIdx.y;
    const int kvh = h >> 2;
    const int tid = threadIdx.x;
    const int lane = tid & 31;
    const int w = tid >> 5;
    const int q0 = qb * 64;
    const float scale = 0.08838834764831845f;
    uint32_t sb = (uint32_t)__cvta_generic_to_shared(sm);

    const int brow = (lane & 7) + ((lane >> 4) << 3);
    const int bch = (lane >> 3) & 1;

    for (int i = tid; i < 2048; i += 128) {
        int mat = i >> 10;
        int idx = i & 1023;
        int r = idx >> 4;
        int c = idx & 15;
        const __nv_bfloat16* src = (mat ? ql : qh) + (size_t)(q0 + r) * HID + h * HD + c * 8;
        *(uint4*)(sm + (mat ? OFF_QL : OFF_QH) + r * QLDT + c * 16) = *(const uint4*)src;
    }

    float m0 = -1e30f, m1 = -1e30f, l0 = 0.f, l1 = 0.f;
    float oa[16][4];
#pragma unroll
    for (int i = 0; i < 16; i++)
#pragma unroll
        for (int t = 0; t < 4; t++) oa[i][t] = 0.f;

    const int r0g = q0 + w * 16 + (lane >> 2);
    const int r1g = r0g + 8;

    for (int kb = 0; kb <= qb; kb++) {
        const int k0 = kb * 64;
        __syncthreads();
        for (int i = tid; i < 2048; i += 128) {
            int mat = i >> 10;
            int idx = i & 1023;
            int r = idx >> 4;
            int c = idx & 15;
            const __nv_bfloat16* src = (mat ? kl : kh) + (size_t)(k0 + r) * KVDIM + kvh * HD + c * 8;
            *(uint4*)(sm + (mat ? OFF_KL : OFF_KH) + r * QLDT + c * 16) = *(const uint4*)src;
        }
        for (int i = tid; i < 2048; i += 128) {
            int mat = i >> 10;
            int idx = i & 1023;
            int r = idx >> 3;
            int c = idx & 7;
            const __nv_bfloat16* src = (mat ? vtl : vth) + (size_t)(kvh * HD + r) * S_LEN + k0 + c * 8;
            *(uint4*)(sm + (mat ? OFF_VL : OFF_VH) + r * VLDT + c * 16) = *(const uint4*)src;
        }
        __syncthreads();

        float s[8][4];
#pragma unroll
        for (int nf = 0; nf < 8; nf++)
#pragma unroll
            for (int t = 0; t < 4; t++) s[nf][t] = 0.f;

#pragma unroll
        for (int kf = 0; kf < 8; kf++) {
            uint32_t aoff = (uint32_t)((w * 16 + (lane & 15)) * QLDT + kf * 32 + (lane >> 4) * 16);
            uint32_t ah[4], al[4];
            ldsm_x4(sb + OFF_QH + aoff, ah[0], ah[1], ah[2], ah[3]);
            ldsm_x4(sb + OFF_QL + aoff, al[0], al[1], al[2], al[3]);
#pragma unroll
            for (int np = 0; np < 4; np++) {
                uint32_t boff = (uint32_t)((np * 16 + brow) * QLDT + kf * 32 + bch * 16);
                uint32_t bh[4], bl[4];
                ldsm_x4(sb + OFF_KH + boff, bh[0], bh[1], bh[2], bh[3]);
                ldsm_x4(sb + OFF_KL + boff, bl[0], bl[1], bl[2], bl[3]);
                mma_bf16(s[np * 2], ah, bh);
                mma_bf16(s[np * 2], ah, bl);
                mma_bf16(s[np * 2], al, bh);
                mma_bf16(s[np * 2 + 1], ah, bh + 2);
                mma_bf16(s[np * 2 + 1], ah, bl + 2);
                mma_bf16(s[np * 2 + 1], al, bh + 2);
            }
        }

#pragma unroll
        for (int nf = 0; nf < 8; nf++)
#pragma unroll
            for (int t = 0; t < 4; t++) s[nf][t] *= scale;
        if (kb == qb) {
#pragma unroll
            for (int nf = 0; nf < 8; nf++) {
                int cg = k0 + nf * 8 + (lane & 3) * 2;
                if (cg > r0g)     s[nf][0] = -1e30f;
                if (cg + 1 > r0g) s[nf][1] = -1e30f;
                if (cg > r1g)     s[nf][2] = -1e30f;
                if (cg + 1 > r1g) s[nf][3] = -1e30f;
            }
        }

        float mx0 = -1e30f, mx1 = -1e30f;
#pragma unroll
        for (int nf = 0; nf < 8; nf++) {
            mx0 = fmaxf(mx0, fmaxf(s[nf][0], s[nf][1]));
            mx1 = fmaxf(mx1, fmaxf(s[nf][2], s[nf][3]));
        }
        mx0 = fmaxf(mx0, __shfl_xor_sync(0xffffffffu, mx0, 1));
        mx0 = fmaxf(mx0, __shfl_xor_sync(0xffffffffu, mx0, 2));
        mx1 = fmaxf(mx1, __shfl_xor_sync(0xffffffffu, mx1, 1));
        mx1 = fmaxf(mx1, __shfl_xor_sync(0xffffffffu, mx1, 2));
        float mn0 = fmaxf(m0, mx0);
        float mn1 = fmaxf(m1, mx1);
        float c0 = __expf(m0 - mn0);
        float c1 = __expf(m1 - mn1);
        m0 = mn0; m1 = mn1;
        float rs0 = 0.f, rs1 = 0.f;
#pragma unroll
        for (int nf = 0; nf < 8; nf++) {
            s[nf][0] = __expf(s[nf][0] - m0); rs0 += s[nf][0];
            s[nf][1] = __expf(s[nf][1] - m0); rs0 += s[nf][1];
            s[nf][2] = __expf(s[nf][2] - m1); rs1 += s[nf][2];
            s[nf][3] = __expf(s[nf][3] - m1); rs1 += s[nf][3];
        }
        rs0 += __shfl_xor_sync(0xffffffffu, rs0, 1);
        rs0 += __shfl_xor_sync(0xffffffffu, rs0, 2);
        rs1 += __shfl_xor_sync(0xffffffffu, rs1, 1);
        rs1 += __shfl_xor_sync(0xffffffffu, rs1, 2);
        l0 = l0 * c0 + rs0;
        l1 = l1 * c1 + rs1;
#pragma unroll
        for (int i = 0; i < 16; i++) {
            oa[i][0] *= c0; oa[i][1] *= c0;
            oa[i][2] *= c1; oa[i][3] *= c1;
        }

        uint32_t ph[8][2], pl[8][2];
#pragma unroll
        for (int nf = 0; nf < 8; nf++) {
            ph[nf][0] = pack_hl(s[nf][0], s[nf][1], pl[nf][0]);
            ph[nf][1] = pack_hl(s[nf][2], s[nf][3], pl[nf][1]);
        }

#pragma unroll
        for (int kf2 = 0; kf2 < 4; kf2++) {
            uint32_t pah[4] = {ph[2 * kf2][0], ph[2 * kf2][1],
                               ph[2 * kf2 + 1][0], ph[2 * kf2 + 1][1]};
            uint32_t pal[4] = {pl[2 * kf2][0], pl[2 * kf2][1],
                               pl[2 * kf2 + 1][0], pl[2 * kf2 + 1][1]};
#pragma unroll
            for (int np = 0; np < 8; np++) {
                uint32_t voff = (uint32_t)((np * 16 + brow) * VLDT + kf2 * 32 + bch * 16);
                uint32_t vh[4], vl[4];
                ldsm_x4(sb + OFF_VH + voff, vh[0], vh[1], vh[2], vh[3]);
                ldsm_x4(sb + OFF_VL + voff, vl[0], vl[1], vl[2], vl[3]);
                mma_bf16(oa[np * 2], pah, vh);
                mma_bf16(oa[np * 2], pah, vl);
                mma_bf16(oa[np * 2], pal, vh);
                mma_bf16(oa[np * 2 + 1], pah, vh + 2);
                mma_bf16(oa[np * 2 + 1], pah, vl + 2);
                mma_bf16(oa[np * 2 + 1], pal, vh + 2);
            }
        }
    }

    // epilogue: normalize, split to bf16 hi/lo, store (fused split for O-proj)
    const float inv0 = 1.0f / l0;
    const float inv1 = 1.0f / l1;
#pragma unroll
    for (int nf2 = 0; nf2 < 16; nf2++) {
        int col = h * HD + nf2 * 8 + (lane & 3) * 2;
        uint32_t lo32, hi32;
        hi32 = pack_hl(oa[nf2][0] * inv0, oa[nf2][1] * inv0, lo32);
        *(uint32_t*)&ohi[(size_t)r0g * HID + col] = hi32;
        *(uint32_t*)&olo[(size_t)r0g * HID + col] = lo32;
        hi32 = pack_hl(oa[nf2][2] * inv1, oa[nf2][3] * inv1, lo32);
        *(uint32_t*)&ohi[(size_t)r1g * HID + col] = hi32;
        *(uint32_t*)&olo[(size_t)r1g * HID + col] = lo32;
    }
}

// ---------------------------------------------------------------------------
// launcher
// ---------------------------------------------------------------------------
extern "C" void kernel_launch(void* const* d_in, const int* in_sizes, int n_in,
                              void* d_out, int out_size) {
    const float* hidden = (const float*)d_in[0];
    const float* cosb = (const float*)d_in[2];
    const float* sinb = (const float*)d_in[3];
    const float* wq = (const float*)d_in[4];
    const float* wk = (const float*)d_in[5];
    const float* wv = (const float*)d_in[6];
    const float* wo = (const float*)d_in[7];
    float* out = (float*)d_out;

    float *q, *k, *v;
    cudaGetSymbolAddress((void**)&q, g_q);
    cudaGetSymbolAddress((void**)&k, g_k);
    cudaGetSymbolAddress((void**)&v, g_v);
    __nv_bfloat16 *hid_hi, *hid_lo, *wq_hi, *wq_lo, *wk_hi, *wk_lo;
    __nv_bfloat16 *wv_hi, *wv_lo, *wo_hi, *wo_lo, *at_hi, *at_lo;
    __nv_bfloat16 *qr_hi, *qr_lo, *kr_hi, *kr_lo, *vt_hi, *vt_lo;
    cudaGetSymbolAddress((void**)&hid_hi, g_hid_hi);
    cudaGetSymbolAddress((void**)&hid_lo, g_hid_lo);
    cudaGetSymbolAddress((void**)&wq_hi, g_wq_hi);
    cudaGetSymbolAddress((void**)&wq_lo, g_wq_lo);
    cudaGetSymbolAddress((void**)&wk_hi, g_wk_hi);
    cudaGetSymbolAddress((void**)&wk_lo, g_wk_lo);
    cudaGetSymbolAddress((void**)&wv_hi, g_wv_hi);
    cudaGetSymbolAddress((void**)&wv_lo, g_wv_lo);
    cudaGetSymbolAddress((void**)&wo_hi, g_wo_hi);
    cudaGetSymbolAddress((void**)&wo_lo, g_wo_lo);
    cudaGetSymbolAddress((void**)&at_hi, g_attn_hi);
    cudaGetSymbolAddress((void**)&at_lo, g_attn_lo);
    cudaGetSymbolAddress((void**)&qr_hi, g_qr_hi);
    cudaGetSymbolAddress((void**)&qr_lo, g_qr_lo);
    cudaGetSymbolAddress((void**)&kr_hi, g_kr_hi);
    cudaGetSymbolAddress((void**)&kr_lo, g_kr_lo);
    cudaGetSymbolAddress((void**)&vt_hi, g_vt_hi);
    cudaGetSymbolAddress((void**)&vt_lo, g_vt_lo);

    // splits (16 elems/thread)
    {
        int n;
        n = S_LEN * HID;
        split_bf16<<<n / (16 * 256), 256>>>(hidden, hid_hi, hid_lo, n);
        n = HID * HID;
        split_bf16<<<n / (16 * 256), 256>>>(wq, wq_hi, wq_lo, n);
        n = KVDIM * HID;
        split_bf16<<<n / (16 * 256), 256>>>(wk, wk_hi, wk_lo, n);
        split_bf16<<<n / (16 * 256), 256>>>(wv, wv_hi, wv_lo, n);
        n = HID * HID;
        split_bf16<<<n / (16 * 256), 256>>>(wo, wo_hi, wo_lo, n);
    }

    cudaFuncSetAttribute(gemm_main, cudaFuncAttributeMaxDynamicSharedMemorySize,
                         GEMM_SMEM);
    cudaFuncSetAttribute(gemm_kv, cudaFuncAttributeMaxDynamicSharedMemorySize,
                         GEMM_SMEM);

    // Q projection; K+V batched
    gemm_main<<<dim3(S_LEN / 128, HID / 128), 256, GEMM_SMEM>>>(
        hid_hi, hid_lo, wq_hi, wq_lo, q, HID, HID);
    gemm_kv<<<dim3(S_LEN / 128, KVDIM / 128, 2), 256, GEMM_SMEM>>>(hid_hi, hid_lo);

    // RoPE + split, V transpose + split
    {
        int total = S_LEN * (NH + NKV) * (HD / 2);
        rope_split<<<(total + 255) / 256, 256>>>(q, k, cosb, sinb,
                                                 qr_hi, qr_lo, kr_hi, kr_lo);
        transpose_split<<<dim3(S_LEN / 32, KVDIM / 32), dim3(32, 8)>>>(v, vt_hi, vt_lo);
    }

    // flash attention (writes bf16 hi/lo directly)
    cudaFuncSetAttribute(flash_tc, cudaFuncAttributeMaxDynamicSharedMemorySize,
                         FLASH_SMEM);
    flash_tc<<<dim3(32, 32), 128, FLASH_SMEM>>>(qr_hi, qr_lo, kr_hi, kr_lo,
                                                vt_hi, vt_lo, at_hi, at_lo);

    // output projection
    gemm_main<<<dim3(S_LEN / 128, HID / 128), 256, GEMM_SMEM>>>(
        at_hi, at_lo, wo_hi, wo_lo, out, HID, HID);
}

// round 6
// speedup vs baseline: 3.6480x; 1.1448x over previous
#include <cuda_runtime.h>
#include <cuda_bf16.h>
#include <stdint.h>

// ---------------------------------------------------------------------------
// LlamaAttention: S=2048, HID=4096, NH=32, NKV=8, D=128
// All matmuls via warp mma.sync bf16x3 (tcgen05 unavailable: PTX target 103).
// ---------------------------------------------------------------------------

#define S_LEN 2048
#define HID   4096
#define NH    32
#define NKV   8
#define HD    128
#define KVDIM (NKV * HD)   // 1024

// fp32 scratch
__device__ float g_q[S_LEN * HID];
__device__ float g_k[S_LEN * KVDIM];
__device__ float g_v[S_LEN * KVDIM];

// bf16 split scratch
__device__ __nv_bfloat16 g_hid_hi[S_LEN * HID];
__device__ __nv_bfloat16 g_hid_lo[S_LEN * HID];
__device__ __nv_bfloat16 g_wq_hi[HID * HID];
__device__ __nv_bfloat16 g_wq_lo[HID * HID];
__device__ __nv_bfloat16 g_wk_hi[KVDIM * HID];
__device__ __nv_bfloat16 g_wk_lo[KVDIM * HID];
__device__ __nv_bfloat16 g_wv_hi[KVDIM * HID];
__device__ __nv_bfloat16 g_wv_lo[KVDIM * HID];
__device__ __nv_bfloat16 g_wo_hi[HID * HID];
__device__ __nv_bfloat16 g_wo_lo[HID * HID];
__device__ __nv_bfloat16 g_attn_hi[S_LEN * HID];
__device__ __nv_bfloat16 g_attn_lo[S_LEN * HID];
__device__ __nv_bfloat16 g_qr_hi[S_LEN * HID];
__device__ __nv_bfloat16 g_qr_lo[S_LEN * HID];
__device__ __nv_bfloat16 g_kr_hi[S_LEN * KVDIM];
__device__ __nv_bfloat16 g_kr_lo[S_LEN * KVDIM];
__device__ __nv_bfloat16 g_vt_hi[KVDIM * S_LEN];
__device__ __nv_bfloat16 g_vt_lo[KVDIM * S_LEN];

// ---------------------------------------------------------------------------
// fused split: hidden + wq + wk + wv + wo in ONE launch. 8 elems/thread.
// ---------------------------------------------------------------------------
#define N_HID (S_LEN * HID)          // 8388608
#define N_WQ  (HID * HID)            // 16777216
#define N_WKV (KVDIM * HID)          // 4194304
#define SEG0  N_HID
#define SEG1  (SEG0 + N_WQ)          // 25165824
#define SEG2  (SEG1 + N_WKV)         // 29360128
#define SEG3  (SEG2 + N_WKV)         // 33554432
#define SEG4  (SEG3 + N_WQ)          // 50331648
#define SPLIT_GRID (SEG4 / (8 * 256))

__device__ __forceinline__ void split8(const float* src, __nv_bfloat16* hi,
                                       __nv_bfloat16* lo, int off) {
    float4 f[2];
    f[0] = *(const float4*)(src + off);
    f[1] = *(const float4*)(src + off + 4);
#pragma unroll
    for (int j = 0; j < 2; j++) {
        __nv_bfloat16 h0 = __float2bfloat16(f[j].x);
        __nv_bfloat16 h1 = __float2bfloat16(f[j].y);
        __nv_bfloat16 h2 = __float2bfloat16(f[j].z);
        __nv_bfloat16 h3 = __float2bfloat16(f[j].w);
        __nv_bfloat16 l0 = __float2bfloat16(f[j].x - __bfloat162float(h0));
        __nv_bfloat16 l1 = __float2bfloat16(f[j].y - __bfloat162float(h1));
        __nv_bfloat16 l2 = __float2bfloat16(f[j].z - __bfloat162float(h2));
        __nv_bfloat16 l3 = __float2bfloat16(f[j].w - __bfloat162float(h3));
        ushort4 hv, lv;
        hv.x = *(unsigned short*)&h0; hv.y = *(unsigned short*)&h1;
        hv.z = *(unsigned short*)&h2; hv.w = *(unsigned short*)&h3;
        lv.x = *(unsigned short*)&l0; lv.y = *(unsigned short*)&l1;
        lv.z = *(unsigned short*)&l2; lv.w = *(unsigned short*)&l3;
        *(ushort4*)(hi + off + j * 4) = hv;
        *(ushort4*)(lo + off + j * 4) = lv;
    }
}

__global__ void split_all(const float* __restrict__ hidden,
                          const float* __restrict__ wq,
                          const float* __restrict__ wk,
                          const float* __restrict__ wv,
                          const float* __restrict__ wo) {
    int g = (blockIdx.x * blockDim.x + threadIdx.x) * 8;
    if (g < SEG0)      split8(hidden, g_hid_hi, g_hid_lo, g);
    else if (g < SEG1) split8(wq, g_wq_hi, g_wq_lo, g - SEG0);
    else if (g < SEG2) split8(wk, g_wk_hi, g_wk_lo, g - SEG1);
    else if (g < SEG3) split8(wv, g_wv_hi, g_wv_lo, g - SEG2);
    else               split8(wo, g_wo_hi, g_wo_lo, g - SEG3);
}

// ---------------------------------------------------------------------------
// warp-MMA primitives
// ---------------------------------------------------------------------------
__device__ __forceinline__ void ldsm_x4(uint32_t addr, uint32_t& r0, uint32_t& r1,
                                        uint32_t& r2, uint32_t& r3) {
    asm volatile("ldmatrix.sync.aligned.m8n8.x4.shared.b16 {%0,%1,%2,%3}, [%4];"
                 : "=r"(r0), "=r"(r1), "=r"(r2), "=r"(r3) : "r"(addr));
}

__device__ __forceinline__ void mma_bf16(float* c, const uint32_t* a, const uint32_t* b) {
    asm volatile(
        "mma.sync.aligned.m16n8k16.row.col.f32.bf16.bf16.f32 "
        "{%0,%1,%2,%3},{%4,%5,%6,%7},{%8,%9},{%0,%1,%2,%3};"
        : "+f"(c[0]), "+f"(c[1]), "+f"(c[2]), "+f"(c[3])
        : "r"(a[0]), "r"(a[1]), "r"(a[2]), "r"(a[3]), "r"(b[0]), "r"(b[1]));
}

// ---------------------------------------------------------------------------
// bf16x3 GEMM body: block tile 256x128, warp tile 64x64, BK=64, 256 threads,
// 2-stage cp.async ring, 144B-padded rows.
// ---------------------------------------------------------------------------
#define GBK  64
#define LDT  144
#define A_T  (256 * LDT)               // 36864
#define B_T  (128 * LDT)               // 18432
#define STG  (2 * A_T + 2 * B_T)       // 110592
#define GEMM_SMEM (2 * STG)            // 221184

__device__ __forceinline__ void gemm_body256(
    const __nv_bfloat16* __restrict__ Ah, const __nv_bfloat16* __restrict__ Al,
    const __nv_bfloat16* __restrict__ Bh, const __nv_bfloat16* __restrict__ Bl,
    float* __restrict__ C, int N, int K, int bm, int bn, char* smem) {
    const int tid = threadIdx.x;
    const int lane = tid & 31;
    const int warp = tid >> 5;
    const int wr = warp >> 1;       // 0..3 (64-row slices)
    const int wc = warp & 1;        // 0..1 (64-col slices)
    uint32_t sbase = (uint32_t)__cvta_generic_to_shared(smem);

    float acc[4][8][4];
#pragma unroll
    for (int mi = 0; mi < 4; mi++)
#pragma unroll
        for (int ni = 0; ni < 8; ni++)
#pragma unroll
            for (int t = 0; t < 4; t++) acc[mi][ni][t] = 0.f;

    auto load_stage = [&](int s, int it) {
        const int kbase = it * GBK;
        uint32_t dst0 = sbase + s * STG;
#pragma unroll
        for (int i = 0; i < 24; i++) {
            int c = tid + i * 256;     // 0..6143
            const __nv_bfloat16* gsrc;
            uint32_t daddr;
            if (c < 4096) {            // A region: Ah then Al
                int mat = c >> 11;     // 0 or 1
                int idx = c & 2047;
                int row = idx >> 3;
                int ch = idx & 7;
                gsrc = (mat ? Al : Ah) + (size_t)(bm + row) * K + kbase + ch * 8;
                daddr = dst0 + mat * A_T + row * LDT + ch * 16;
            } else {                   // B region: Bh then Bl
                int cb = c - 4096;
                int mat = cb >> 10;    // 0 or 1
                int idx = cb & 1023;
                int row = idx >> 3;
                int ch = idx & 7;
                gsrc = (mat ? Bl : Bh) + (size_t)(bn + row) * K + kbase + ch * 8;
                daddr = dst0 + 2 * A_T + mat * B_T + row * LDT + ch * 16;
            }
            asm volatile("cp.async.cg.shared.global [%0], [%1], 16;"
                         :: "r"(daddr), "l"(gsrc));
        }
        asm volatile("cp.async.commit_group;");
    };

    const int NIT = K / GBK;
    load_stage(0, 0);
    load_stage(1, 1);

    const int brow = (lane & 7) + ((lane >> 4) << 3);
    const int bch = (lane >> 3) & 1;

    for (int it = 0; it < NIT; it++) {
        asm volatile("cp.async.wait_group 1;");
        __syncthreads();

        uint32_t sa = sbase + (it & 1) * STG;
#pragma unroll
        for (int ks = 0; ks < 4; ks++) {
            uint32_t ah[4][4], al[4][4];
#pragma unroll
            for (int mi = 0; mi < 4; mi++) {
                uint32_t off = (uint32_t)((wr * 64 + mi * 16 + (lane & 15)) * LDT +
                                          ks * 32 + ((lane >> 4) & 1) * 16);
                ldsm_x4(sa + off, ah[mi][0], ah[mi][1], ah[mi][2], ah[mi][3]);
                ldsm_x4(sa + A_T + off, al[mi][0], al[mi][1], al[mi][2], al[mi][3]);
            }
#pragma unroll
            for (int half = 0; half < 2; half++) {
                uint32_t bh[4][2], bl[4][2];
#pragma unroll
                for (int np = 0; np < 2; np++) {
                    uint32_t off = (uint32_t)((wc * 64 + half * 32 + np * 16 + brow) * LDT +
                                              ks * 32 + bch * 16);
                    uint32_t r0, r1, r2, r3;
                    ldsm_x4(sa + 2 * A_T + off, r0, r1, r2, r3);
                    bh[np * 2][0] = r0; bh[np * 2][1] = r1;
                    bh[np * 2 + 1][0] = r2; bh[np * 2 + 1][1] = r3;
                    ldsm_x4(sa + 2 * A_T + B_T + off, r0, r1, r2, r3);
                    bl[np * 2][0] = r0; bl[np * 2][1] = r1;
                    bl[np * 2 + 1][0] = r2; bl[np * 2 + 1][1] = r3;
                }
#pragma unroll
                for (int mi = 0; mi < 4; mi++)
#pragma unroll
                    for (int nf = 0; nf < 4; nf++) {
                        float* a = acc[mi][half * 4 + nf];
                        mma_bf16(a, ah[mi], bh[nf]);
                        mma_bf16(a, ah[mi], bl[nf]);
                        mma_bf16(a, al[mi], bh[nf]);
                    }
            }
        }
        __syncthreads();
        if (it + 2 < NIT) load_stage(it & 1, it + 2);
        else              asm volatile("cp.async.commit_group;");
    }

#pragma unroll
    for (int mi = 0; mi < 4; mi++) {
        const int r0 = bm + wr * 64 + mi * 16 + (lane >> 2);
#pragma unroll
        for (int ni = 0; ni < 8; ni++) {
            const int col = bn + wc * 64 + ni * 8 + (lane & 3) * 2;
            *(float2*)&C[(size_t)r0 * N + col] = make_float2(acc[mi][ni][0], acc[mi][ni][1]);
            *(float2*)&C[(size_t)(r0 + 8) * N + col] = make_float2(acc[mi][ni][2], acc[mi][ni][3]);
        }
    }
}

// fused QKV projection: grid (M/256=8, 48). bn-mapped to wq/wk/wv.
__global__ __launch_bounds__(256, 1) void gemm_qkv() {
    extern __shared__ char smem[];
    const int bng = blockIdx.y * 128;
    const int bm = blockIdx.x * 256;
    if (bng < HID) {
        gemm_body256(g_hid_hi, g_hid_lo, g_wq_hi, g_wq_lo, g_q, HID, HID,
                     bm, bng, smem);
    } else if (bng < HID + KVDIM) {
        gemm_body256(g_hid_hi, g_hid_lo, g_wk_hi, g_wk_lo, g_k, KVDIM, HID,
                     bm, bng - HID, smem);
    } else {
        gemm_body256(g_hid_hi, g_hid_lo, g_wv_hi, g_wv_lo, g_v, KVDIM, HID,
                     bm, bng - HID - KVDIM, smem);
    }
}

// output projection
__global__ __launch_bounds__(256, 1) void gemm_o(float* __restrict__ out) {
    extern __shared__ char smem[];
    gemm_body256(g_attn_hi, g_attn_lo, g_wo_hi, g_wo_lo, out, HID, HID,
                 blockIdx.x * 256, blockIdx.y * 128, smem);
}

// ---------------------------------------------------------------------------
// RoPE + split
// ---------------------------------------------------------------------------
__global__ void rope_split(const float* __restrict__ q, const float* __restrict__ k,
                           const float* __restrict__ cosb, const float* __restrict__ sinb,
                           __nv_bfloat16* __restrict__ qh, __nv_bfloat16* __restrict__ ql,
                           __nv_bfloat16* __restrict__ kh, __nv_bfloat16* __restrict__ kl) {
    int idx = blockIdx.x * blockDim.x + threadIdx.x;
    const int total = S_LEN * (NH + NKV) * (HD / 2);
    if (idx >= total) return;
    int i = idx & 63;
    int h = (idx >> 6) % (NH + NKV);
    int s = idx / (64 * (NH + NKV));
    float c  = cosb[s * 64 + i];
    float sn = sinb[s * 64 + i];
    const float* base;
    __nv_bfloat16 *oh, *ol;
    if (h < NH) {
        size_t off = (size_t)s * HID + h * HD;
        base = q + off; oh = qh + off; ol = ql + off;
    } else {
        size_t off = (size_t)s * KVDIM + (h - NH) * HD;
        base = k + off; oh = kh + off; ol = kl + off;
    }
    float a = base[2 * i];
    float b = base[2 * i + 1];
    float x = a * c - b * sn;
    float y = a * sn + b * c;
    __nv_bfloat162 hv = __floats2bfloat162_rn(x, y);
    float rx = x - __bfloat162float(hv.x);
    float ry = y - __bfloat162float(hv.y);
    __nv_bfloat162 lv = __floats2bfloat162_rn(rx, ry);
    *(__nv_bfloat162*)(oh + 2 * i) = hv;
    *(__nv_bfloat162*)(ol + 2 * i) = lv;
}

// ---------------------------------------------------------------------------
// transpose + split: v[S,1024] fp32 -> vT hi/lo [1024, S]
// ---------------------------------------------------------------------------
__global__ void transpose_split(const float* __restrict__ v,
                                __nv_bfloat16* __restrict__ th,
                                __nv_bfloat16* __restrict__ tl) {
    __shared__ float tile[32][33];
    const int bs = blockIdx.x * 32;
    const int bd = blockIdx.y * 32;
    const int tx = threadIdx.x;
    const int ty = threadIdx.y;
#pragma unroll
    for (int i = 0; i < 4; i++) {
        int sy = ty * 4 + i;
        tile[sy][tx] = v[(size_t)(bs + sy) * KVDIM + bd + tx];
    }
    __syncthreads();
#pragma unroll
    for (int i = 0; i < 4; i++) {
        int dy = ty * 4 + i;
        float val = tile[tx][dy];
        __nv_bfloat16 h = __float2bfloat16(val);
        __nv_bfloat16 l = __float2bfloat16(val - __bfloat162float(h));
        th[(size_t)(bd + dy) * S_LEN + bs + tx] = h;
        tl[(size_t)(bd + dy) * S_LEN + bs + tx] = l;
    }
}

// ---------------------------------------------------------------------------
// Flash attention (bf16x3, warp MMA), cp.async double-buffered K/V.
// Grid (32 qb reversed, 32 h), 128 threads.
// ---------------------------------------------------------------------------
#define QLDT 272
#define VLDT 144
#define F_QH 0
#define F_QL 17408
#define F_K(s) (34816 + (s) * 34816)    // KH at +0, KL at +17408
#define F_V(s) (104448 + (s) * 36864)   // VH at +0, VL at +18432
#define FLASH_SMEM (104448 + 2 * 36864) // 178176

__device__ __forceinline__ uint32_t pack_hl(float f0, float f1, uint32_t& lo) {
    __nv_bfloat162 h = __floats2bfloat162_rn(f0, f1);
    float r0 = f0 - __bfloat162float(h.x);
    float r1 = f1 - __bfloat162float(h.y);
    __nv_bfloat162 l = __floats2bfloat162_rn(r0, r1);
    lo = *(uint32_t*)&l;
    return *(uint32_t*)&h;
}

__global__ __launch_bounds__(128, 1) void flash_tc(
    const __nv_bfloat16* __restrict__ qh, const __nv_bfloat16* __restrict__ ql,
    const __nv_bfloat16* __restrict__ kh, const __nv_bfloat16* __restrict__ kl,
    const __nv_bfloat16* __restrict__ vth, const __nv_bfloat16* __restrict__ vtl,
    __nv_bfloat16* __restrict__ ohi, __nv_bfloat16* __restrict__ olo) {
    extern __shared__ char sm[];
    const int qb = (int)gridDim.x - 1 - (int)blockIdx.x;
    const int h  = blockIdx.y;
    const int kvh = h >> 2;
    const int tid = threadIdx.x;
    const int lane = tid & 31;
    const int w = tid >> 5;
    const int q0 = qb * 64;
    const float scale = 0.08838834764831845f;
    uint32_t sb = (uint32_t)__cvta_generic_to_shared(sm);

    const int brow = (lane & 7) + ((lane >> 4) << 3);
    const int bch = (lane >> 3) & 1;

    // Q tiles (plain stores; covered by first loop barrier)
    for (int i = tid; i < 2048; i += 128) {
        int mat = i >> 10;
        int idx = i & 1023;
        int r = idx >> 4;
        int c = idx & 15;
        const __nv_bfloat16* src = (mat ? ql : qh) + (size_t)(q0 + r) * HID + h * HD + c * 8;
        *(uint4*)(sm + (mat ? F_QL : F_QH) + r * QLDT + c * 16) = *(const uint4*)src;
    }

    auto preload = [&](int kb) {
        const int k0 = kb * 64;
        const int s = kb & 1;
        uint32_t kdst = sb + F_K(s);
        uint32_t vdst = sb + F_V(s);
#pragma unroll
        for (int i0 = 0; i0 < 16; i0++) {
            int i = tid + i0 * 128;
            int mat = i >> 10;
            int idx = i & 1023;
            int r = idx >> 4;
            int c = idx & 15;
            const void* src = (mat ? kl : kh) + (size_t)(k0 + r) * KVDIM + kvh * HD + c * 8;
            asm volatile("cp.async.cg.shared.global [%0], [%1], 16;"
                         :: "r"(kdst + mat * 17408 + r * QLDT + c * 16), "l"(src));
        }
#pragma unroll
        for (int i0 = 0; i0 < 16; i0++) {
            int i = tid + i0 * 128;
            int mat = i >> 10;
            int idx = i & 1023;
            int r = idx >> 3;
            int c = idx & 7;
            const void* src = (mat ? vtl : vth) + (size_t)(kvh * HD + r) * S_LEN + k0 + c * 8;
            asm volatile("cp.async.cg.shared.global [%0], [%1], 16;"
                         :: "r"(vdst + mat * 18432 + r * VLDT + c * 16), "l"(src));
        }
        asm volatile("cp.async.commit_group;");
    };

    float m0 = -1e30f, m1 = -1e30f, l0 = 0.f, l1 = 0.f;
    float oa[16][4];
#pragma unroll
    for (int i = 0; i < 16; i++)
#pragma unroll
        for (int t = 0; t < 4; t++) oa[i][t] = 0.f;

    const int r0g = q0 + w * 16 + (lane >> 2);
    const int r1g = r0g + 8;

    preload(0);

    for (int kb = 0; kb <= qb; kb++) {
        const int k0 = kb * 64;
        if (kb + 1 <= qb) {
            preload(kb + 1);
            asm volatile("cp.async.wait_group 1;");
        } else {
            asm volatile("cp.async.wait_group 0;");
        }
        __syncthreads();

        const uint32_t kbase = sb + F_K(kb & 1);
        const uint32_t vbase = sb + F_V(kb & 1);

        float s[8][4];
#pragma unroll
        for (int nf = 0; nf < 8; nf++)
#pragma unroll
            for (int t = 0; t < 4; t++) s[nf][t] = 0.f;

#pragma unroll
        for (int kf = 0; kf < 8; kf++) {
            uint32_t aoff = (uint32_t)((w * 16 + (lane & 15)) * QLDT + kf * 32 + (lane >> 4) * 16);
            uint32_t ah[4], al[4];
            ldsm_x4(sb + F_QH + aoff, ah[0], ah[1], ah[2], ah[3]);
            ldsm_x4(sb + F_QL + aoff, al[0], al[1], al[2], al[3]);
#pragma unroll
            for (int np = 0; np < 4; np++) {
                uint32_t boff = (uint32_t)((np * 16 + brow) * QLDT + kf * 32 + bch * 16);
                uint32_t bh[4], bl[4];
                ldsm_x4(kbase + boff, bh[0], bh[1], bh[2], bh[3]);
                ldsm_x4(kbase + 17408 + boff, bl[0], bl[1], bl[2], bl[3]);
                mma_bf16(s[np * 2], ah, bh);
                mma_bf16(s[np * 2], ah, bl);
                mma_bf16(s[np * 2], al, bh);
                mma_bf16(s[np * 2 + 1], ah, bh + 2);
                mma_bf16(s[np * 2 + 1], ah, bl + 2);
                mma_bf16(s[np * 2 + 1], al, bh + 2);
            }
        }

#pragma unroll
        for (int nf = 0; nf < 8; nf++)
#pragma unroll
            for (int t = 0; t < 4; t++) s[nf][t] *= scale;
        if (kb == qb) {
#pragma unroll
            for (int nf = 0; nf < 8; nf++) {
                int cg = k0 + nf * 8 + (lane & 3) * 2;
                if (cg > r0g)     s[nf][0] = -1e30f;
                if (cg + 1 > r0g) s[nf][1] = -1e30f;
                if (cg > r1g)     s[nf][2] = -1e30f;
                if (cg + 1 > r1g) s[nf][3] = -1e30f;
            }
        }

        float mx0 = -1e30f, mx1 = -1e30f;
#pragma unroll
        for (int nf = 0; nf < 8; nf++) {
            mx0 = fmaxf(mx0, fmaxf(s[nf][0], s[nf][1]));
            mx1 = fmaxf(mx1, fmaxf(s[nf][2], s[nf][3]));
        }
        mx0 = fmaxf(mx0, __shfl_xor_sync(0xffffffffu, mx0, 1));
        mx0 = fmaxf(mx0, __shfl_xor_sync(0xffffffffu, mx0, 2));
        mx1 = fmaxf(mx1, __shfl_xor_sync(0xffffffffu, mx1, 1));
        mx1 = fmaxf(mx1, __shfl_xor_sync(0xffffffffu, mx1, 2));
        float mn0 = fmaxf(m0, mx0);
        float mn1 = fmaxf(m1, mx1);
        float c0 = __expf(m0 - mn0);
        float c1 = __expf(m1 - mn1);
        m0 = mn0; m1 = mn1;
        float rs0 = 0.f, rs1 = 0.f;
#pragma unroll
        for (int nf = 0; nf < 8; nf++) {
            s[nf][0] = __expf(s[nf][0] - m0); rs0 += s[nf][0];
            s[nf][1] = __expf(s[nf][1] - m0); rs0 += s[nf][1];
            s[nf][2] = __expf(s[nf][2] - m1); rs1 += s[nf][2];
            s[nf][3] = __expf(s[nf][3] - m1); rs1 += s[nf][3];
        }
        rs0 += __shfl_xor_sync(0xffffffffu, rs0, 1);
        rs0 += __shfl_xor_sync(0xffffffffu, rs0, 2);
        rs1 += __shfl_xor_sync(0xffffffffu, rs1, 1);
        rs1 += __shfl_xor_sync(0xffffffffu, rs1, 2);
        l0 = l0 * c0 + rs0;
        l1 = l1 * c1 + rs1;
#pragma unroll
        for (int i = 0; i < 16; i++) {
            oa[i][0] *= c0; oa[i][1] *= c0;
            oa[i][2] *= c1; oa[i][3] *= c1;
        }

        uint32_t ph[8][2], pl[8][2];
#pragma unroll
        for (int nf = 0; nf < 8; nf++) {
            ph[nf][0] = pack_hl(s[nf][0], s[nf][1], pl[nf][0]);
            ph[nf][1] = pack_hl(s[nf][2], s[nf][3], pl[nf][1]);
        }

#pragma unroll
        for (int kf2 = 0; kf2 < 4; kf2++) {
            uint32_t pah[4] = {ph[2 * kf2][0], ph[2 * kf2][1],
                               ph[2 * kf2 + 1][0], ph[2 * kf2 + 1][1]};
            uint32_t pal[4] = {pl[2 * kf2][0], pl[2 * kf2][1],
                               pl[2 * kf2 + 1][0], pl[2 * kf2 + 1][1]};
#pragma unroll
            for (int np = 0; np < 8; np++) {
                uint32_t voff = (uint32_t)((np * 16 + brow) * VLDT + kf2 * 32 + bch * 16);
                uint32_t vh[4], vl[4];
                ldsm_x4(vbase + voff, vh[0], vh[1], vh[2], vh[3]);
                ldsm_x4(vbase + 18432 + voff, vl[0], vl[1], vl[2], vl[3]);
                mma_bf16(oa[np * 2], pah, vh);
                mma_bf16(oa[np * 2], pah, vl);
                mma_bf16(oa[np * 2], pal, vh);
                mma_bf16(oa[np * 2 + 1], pah, vh + 2);
                mma_bf16(oa[np * 2 + 1], pah, vl + 2);
                mma_bf16(oa[np * 2 + 1], pal, vh + 2);
            }
        }
        __syncthreads();
    }

    const float inv0 = 1.0f / l0;
    const float inv1 = 1.0f / l1;
#pragma unroll
    for (int nf2 = 0; nf2 < 16; nf2++) {
        int col = h * HD + nf2 * 8 + (lane & 3) * 2;
        uint32_t lo32, hi32;
        hi32 = pack_hl(oa[nf2][0] * inv0, oa[nf2][1] * inv0, lo32);
        *(uint32_t*)&ohi[(size_t)r0g * HID + col] = hi32;
        *(uint32_t*)&olo[(size_t)r0g * HID + col] = lo32;
        hi32 = pack_hl(oa[nf2][2] * inv1, oa[nf2][3] * inv1, lo32);
        *(uint32_t*)&ohi[(size_t)r1g * HID + col] = hi32;
        *(uint32_t*)&olo[(size_t)r1g * HID + col] = lo32;
    }
}

// ---------------------------------------------------------------------------
// launcher
// ---------------------------------------------------------------------------
extern "C" void kernel_launch(void* const* d_in, const int* in_sizes, int n_in,
                              void* d_out, int out_size) {
    const float* hidden = (const float*)d_in[0];
    const float* cosb = (const float*)d_in[2];
    const float* sinb = (const float*)d_in[3];
    const float* wq = (const float*)d_in[4];
    const float* wk = (const float*)d_in[5];
    const float* wv = (const float*)d_in[6];
    const float* wo = (const float*)d_in[7];
    float* out = (float*)d_out;

    float *q, *k, *v;
    cudaGetSymbolAddress((void**)&q, g_q);
    cudaGetSymbolAddress((void**)&k, g_k);
    cudaGetSymbolAddress((void**)&v, g_v);
    __nv_bfloat16 *at_hi, *at_lo, *qr_hi, *qr_lo, *kr_hi, *kr_lo, *vt_hi, *vt_lo;
    cudaGetSymbolAddress((void**)&at_hi, g_attn_hi);
    cudaGetSymbolAddress((void**)&at_lo, g_attn_lo);
    cudaGetSymbolAddress((void**)&qr_hi, g_qr_hi);
    cudaGetSymbolAddress((void**)&qr_lo, g_qr_lo);
    cudaGetSymbolAddress((void**)&kr_hi, g_kr_hi);
    cudaGetSymbolAddress((void**)&kr_lo, g_kr_lo);
    cudaGetSymbolAddress((void**)&vt_hi, g_vt_hi);
    cudaGetSymbolAddress((void**)&vt_lo, g_vt_lo);

    // single fused split
    split_all<<<SPLIT_GRID, 256>>>(hidden, wq, wk, wv, wo);

    cudaFuncSetAttribute(gemm_qkv, cudaFuncAttributeMaxDynamicSharedMemorySize,
                         GEMM_SMEM);
    cudaFuncSetAttribute(gemm_o, cudaFuncAttributeMaxDynamicSharedMemorySize,
                         GEMM_SMEM);

    // fused QKV projection: 48 N-tiles = 32 (Q) + 8 (K) + 8 (V)
    gemm_qkv<<<dim3(S_LEN / 256, 48), 256, GEMM_SMEM>>>();

    // RoPE + split, V transpose + split
    {
        int total = S_LEN * (NH + NKV) * (HD / 2);
        rope_split<<<(total + 255) / 256, 256>>>(q, k, cosb, sinb,
                                                 qr_hi, qr_lo, kr_hi, kr_lo);
        transpose_split<<<dim3(S_LEN / 32, KVDIM / 32), dim3(32, 8)>>>(v, vt_hi, vt_lo);
    }

    // flash attention (double-buffered K/V, writes bf16 hi/lo)
    cudaFuncSetAttribute(flash_tc, cudaFuncAttributeMaxDynamicSharedMemorySize,
                         FLASH_SMEM);
    flash_tc<<<dim3(32, 32), 128, FLASH_SMEM>>>(qr_hi, qr_lo, kr_hi, kr_lo,
                                                vt_hi, vt_lo, at_hi, at_lo);

    // output projection
    gemm_o<<<dim3(S_LEN / 256, HID / 128), 256, GEMM_SMEM>>>(out);
}